// round 3
// baseline (speedup 1.0000x reference)
#include <cuda_runtime.h>
#include <math.h>

#define D 300
#define D2 600
#define LAYERS 5
#define MAXN 200000
#define MAXG 1024
#define BN_EPS 1e-5f

// ---------------- scratch (static device globals; no allocation) ----------------
__device__ float g_h[(size_t)MAXN * D];     // node features   [N,300]
__device__ float g_agg[(size_t)MAXN * D];   // aggregated msgs [N,300]
__device__ float g_t[(size_t)MAXN * D2];    // MLP hidden      [N,600]
__device__ float g_gsum[(size_t)MAXG * D];  // graph sums      [G,300]
__device__ float g_cnt[MAXG];               // graph node counts

// ---------------- input node embedding: h = ne0[an] + ne1[ct] ----------------
// warp per node, 8 warps per block
__global__ void node_init_kernel(const int* __restrict__ an, const int* __restrict__ ct,
                                 const float* __restrict__ ne0, const float* __restrict__ ne1,
                                 float* __restrict__ h, int N) {
    int i = blockIdx.x * 8 + (threadIdx.x >> 5);
    if (i >= N) return;
    int lane = threadIdx.x & 31;
    const float* p0 = ne0 + (size_t)an[i] * D;
    const float* p1 = ne1 + (size_t)ct[i] * D;
    float* out = h + (size_t)i * D;
    for (int d = lane; d < D; d += 32)
        out[d] = p0[d] + p1[d];
}

// ---------------- edge message + scatter-add onto dst ----------------
// agg[dst[e]] += h[src[e]] + ee0[bt[e]] + ee1[bd[e]]
// warp per edge, 8 warps per block
__global__ void edge_message_kernel(const float* __restrict__ h,
                                    const float* __restrict__ ee0, const float* __restrict__ ee1,
                                    const int* __restrict__ bt, const int* __restrict__ bd,
                                    const int* __restrict__ src, const int* __restrict__ dst,
                                    float* __restrict__ agg, int E) {
    int e = blockIdx.x * 8 + (threadIdx.x >> 5);
    if (e >= E) return;
    int lane = threadIdx.x & 31;
    const float* p0 = ee0 + (size_t)bt[e] * D;
    const float* p1 = ee1 + (size_t)bd[e] * D;
    const float* hs = h + (size_t)src[e] * D;
    float* out = agg + (size_t)dst[e] * D;
    for (int d = lane; d < D; d += 32)
        atomicAdd(&out[d], hs[d] + p0[d] + p1[d]);
}

// ---------------- fp32 tiled GEMM with fused epilogue ----------------
// C[M,NC] = epi(A[M,K] @ B[K,NC] + bias)
// mode 0: relu(x+bias)                 (GIN hidden layer)
// mode 1: BN(x+bias)                   (last layer)
// mode 2: relu(BN(x+bias))             (intermediate layers)
template<int BM, int BN, int BK, int TM, int TN>
__global__ void gemm_epi_kernel(const float* __restrict__ A, const float* __restrict__ B,
                                const float* __restrict__ bias, float* __restrict__ C,
                                int M, int K, int NC, int mode,
                                const float* __restrict__ bn_gamma,
                                const float* __restrict__ bn_beta,
                                const float* __restrict__ bn_mean,
                                const float* __restrict__ bn_var) {
    __shared__ float As[BK][BM + 4];   // +4 pad: avoid bank conflicts on transposed stores
    __shared__ float Bs[BK][BN];

    const int tid = threadIdx.x;                // 256 threads
    const int tx = tid % (BN / TN);             // 16
    const int ty = tid / (BN / TN);             // 16
    const int row_base = blockIdx.y * BM;
    const int col_base = blockIdx.x * BN;
    const int row0 = row_base + ty * TM;
    const int col0 = col_base + tx * TN;

    float acc[TM][TN];
#pragma unroll
    for (int m = 0; m < TM; m++)
#pragma unroll
        for (int n = 0; n < TN; n++) acc[m][n] = 0.0f;

    for (int k0 = 0; k0 < K; k0 += BK) {
        // load A tile (transposed into smem): BM*BK elems
#pragma unroll
        for (int i = tid; i < BM * BK; i += 256) {
            int r = i / BK, c = i % BK;
            int gr = row_base + r;
            As[c][r] = (gr < M) ? A[(size_t)gr * K + (k0 + c)] : 0.0f;
        }
        // load B tile: BK*BN elems
#pragma unroll
        for (int i = tid; i < BK * BN; i += 256) {
            int r = i / BN, c = i % BN;
            int gc = col_base + c;
            Bs[r][c] = (gc < NC) ? B[(size_t)(k0 + r) * NC + gc] : 0.0f;
        }
        __syncthreads();

#pragma unroll
        for (int kk = 0; kk < BK; kk++) {
            float4 a0 = *reinterpret_cast<const float4*>(&As[kk][ty * TM]);
            float4 a1 = *reinterpret_cast<const float4*>(&As[kk][ty * TM + 4]);
            float4 b0 = *reinterpret_cast<const float4*>(&Bs[kk][tx * TN]);
            float af[TM] = {a0.x, a0.y, a0.z, a0.w, a1.x, a1.y, a1.z, a1.w};
            float bf[TN] = {b0.x, b0.y, b0.z, b0.w};
#pragma unroll
            for (int m = 0; m < TM; m++)
#pragma unroll
                for (int n = 0; n < TN; n++)
                    acc[m][n] = fmaf(af[m], bf[n], acc[m][n]);
        }
        __syncthreads();
    }

    // per-column epilogue params
    float bia[TN], sc[TN], bb[TN], mn[TN];
#pragma unroll
    for (int n = 0; n < TN; n++) {
        int c = col0 + n;
        if (c < NC) {
            bia[n] = bias[c];
            if (mode >= 1) {
                sc[n] = bn_gamma[c] * rsqrtf(bn_var[c] + BN_EPS);
                bb[n] = bn_beta[c];
                mn[n] = bn_mean[c];
            }
        }
    }

#pragma unroll
    for (int m = 0; m < TM; m++) {
        int r = row0 + m;
        if (r >= M) continue;
        float* crow = C + (size_t)r * NC;
#pragma unroll
        for (int n = 0; n < TN; n++) {
            int c = col0 + n;
            if (c >= NC) continue;
            float x = acc[m][n] + bia[n];
            if (mode == 0) {
                x = fmaxf(x, 0.0f);
            } else {
                x = (x - mn[n]) * sc[n] + bb[n];
                if (mode == 2) x = fmaxf(x, 0.0f);
            }
            crow[c] = x;
        }
    }
}

// ---------------- average-pool accumulation ----------------
// warp per node, 8 warps per block
__global__ void pool_kernel(const float* __restrict__ h, const int* __restrict__ gid,
                            float* __restrict__ gsum, float* __restrict__ cnt, int N) {
    int i = blockIdx.x * 8 + (threadIdx.x >> 5);
    if (i >= N) return;
    int lane = threadIdx.x & 31;
    int g = gid[i];
    const float* hr = h + (size_t)i * D;
    float* out = gsum + (size_t)g * D;
    for (int d = lane; d < D; d += 32)
        atomicAdd(&out[d], hr[d]);
    if (lane == 0)
        atomicAdd(&cnt[g], 1.0f);
}

// ---------------- head: out[g] = (gsum[g]/max(cnt,1)) @ Wd + bd ----------------
__global__ void head_kernel(const float* __restrict__ gsum, const float* __restrict__ cnt,
                            const float* __restrict__ Wd, const float* __restrict__ bd,
                            float* __restrict__ out, int G) {
    __shared__ float row[D];
    int g = blockIdx.x;
    if (g >= G) return;
    float inv = 1.0f / fmaxf(cnt[g], 1.0f);
    for (int k = threadIdx.x; k < D; k += blockDim.x)
        row[k] = gsum[(size_t)g * D + k] * inv;
    __syncthreads();
    int c = threadIdx.x;  // 256 threads == 256 output cols
    float acc = bd[c];
#pragma unroll 4
    for (int k = 0; k < D; k++)
        acc = fmaf(row[k], Wd[(size_t)k * 256 + c], acc);
    out[(size_t)g * 256 + c] = acc;
}

// ---------------- launch ----------------
extern "C" void kernel_launch(void* const* d_in, const int* in_sizes, int n_in,
                              void* d_out, int out_size) {
    const int*   atomic_number = (const int*)d_in[0];
    const int*   chirality     = (const int*)d_in[1];
    const int*   bond_type     = (const int*)d_in[2];
    const int*   bond_dir      = (const int*)d_in[3];
    const int*   src           = (const int*)d_in[4];
    const int*   dst           = (const int*)d_in[5];
    const int*   gid           = (const int*)d_in[6];
    /* d_in[7] = num_graphs (device scalar) -- G known from out_size */
    const float* ne0           = (const float*)d_in[8];
    const float* ne1           = (const float*)d_in[9];
    const float* ee0           = (const float*)d_in[10];
    const float* ee1           = (const float*)d_in[11];
    const float* W1            = (const float*)d_in[12];
    const float* b1            = (const float*)d_in[13];
    const float* W2            = (const float*)d_in[14];
    const float* b2            = (const float*)d_in[15];
    const float* gamma         = (const float*)d_in[16];
    const float* beta          = (const float*)d_in[17];
    const float* mean          = (const float*)d_in[18];
    const float* var           = (const float*)d_in[19];
    const float* Wd            = (const float*)d_in[20];
    const float* bd            = (const float*)d_in[21];
    float* out = (float*)d_out;

    int N = in_sizes[0];
    int E = in_sizes[2];
    int G = out_size / 256;
    if (N > MAXN) N = MAXN;
    if (G > MAXG) G = MAXG;

    float *h_ptr, *agg_ptr, *t_ptr, *gsum_ptr, *cnt_ptr;
    cudaGetSymbolAddress((void**)&h_ptr, g_h);
    cudaGetSymbolAddress((void**)&agg_ptr, g_agg);
    cudaGetSymbolAddress((void**)&t_ptr, g_t);
    cudaGetSymbolAddress((void**)&gsum_ptr, g_gsum);
    cudaGetSymbolAddress((void**)&cnt_ptr, g_cnt);

    node_init_kernel<<<(N + 7) / 8, 256>>>(atomic_number, chirality, ne0, ne1, h_ptr, N);

    for (int l = 0; l < LAYERS; l++) {
        cudaMemsetAsync(agg_ptr, 0, (size_t)N * D * sizeof(float));
        edge_message_kernel<<<(E + 7) / 8, 256>>>(h_ptr,
                                                  ee0 + (size_t)l * 6 * D,
                                                  ee1 + (size_t)l * 3 * D,
                                                  bond_type, bond_dir, src, dst, agg_ptr, E);
        // GEMM1: t = relu(agg @ W1[l] + b1[l])   [N,300]x[300,600]
        {
            dim3 grid((D2 + 63) / 64, (N + 127) / 128);
            gemm_epi_kernel<128, 64, 12, 8, 4><<<grid, 256>>>(
                agg_ptr, W1 + (size_t)l * D * D2, b1 + (size_t)l * D2, t_ptr,
                N, D, D2, /*mode=*/0, nullptr, nullptr, nullptr, nullptr);
        }
        // GEMM2: h = [relu](BN(t @ W2[l] + b2[l]))   [N,600]x[600,300]
        {
            dim3 grid((D + 63) / 64, (N + 127) / 128);
            int mode = (l < LAYERS - 1) ? 2 : 1;
            gemm_epi_kernel<128, 64, 12, 8, 4><<<grid, 256>>>(
                t_ptr, W2 + (size_t)l * D2 * D, b2 + (size_t)l * D, h_ptr,
                N, D2, D, mode,
                gamma + (size_t)l * D, beta + (size_t)l * D,
                mean + (size_t)l * D, var + (size_t)l * D);
        }
    }

    cudaMemsetAsync(gsum_ptr, 0, (size_t)G * D * sizeof(float));
    cudaMemsetAsync(cnt_ptr, 0, (size_t)G * sizeof(float));
    pool_kernel<<<(N + 7) / 8, 256>>>(h_ptr, gid, gsum_ptr, cnt_ptr, N);
    head_kernel<<<G, 256>>>(gsum_ptr, cnt_ptr, Wd, bd, out, G);
}

// round 7
// speedup vs baseline: 2.2773x; 2.2773x over previous
#include <cuda_runtime.h>
#include <cuda_bf16.h>
#include <math.h>
#include <stdint.h>

#define D 300
#define D2 600
#define LAYERS 5
#define MAXN 200000
#define MAXG 1024
#define BN_EPS 1e-5f

// ---- GEMM tiling ----
#define BM 128
#define BN 128
#define BK 32
#define LDK 40           // padded SMEM row length (bf16 units): 80B stride, conflict-free ldmatrix
#define K1P 320          // GEMM1 K=300 padded to BK multiple
#define K2P 640          // GEMM2 K=600 padded
#define N1P 640          // GEMM1 NC=600 padded (5 col tiles)
#define N2P 384          // GEMM2 NC=300 padded (3 col tiles)

// ---------------- scratch (static device globals) ----------------
__device__ float g_h[(size_t)MAXN * D];
__device__ float g_agg[(size_t)MAXN * D];
__device__ float g_t[(size_t)MAXN * D2];
__device__ float g_gsum[(size_t)MAXG * D];
__device__ float g_cnt[MAXG];
__device__ __nv_bfloat16 g_w1h[(size_t)LAYERS * N1P * K1P];
__device__ __nv_bfloat16 g_w1l[(size_t)LAYERS * N1P * K1P];
__device__ __nv_bfloat16 g_w2h[(size_t)LAYERS * N2P * K2P];
__device__ __nv_bfloat16 g_w2l[(size_t)LAYERS * N2P * K2P];

// ---------------- helpers ----------------
__device__ __forceinline__ uint32_t smem_u32(const void* p) {
    uint32_t a;
    asm("{ .reg .u64 t; cvta.to.shared.u64 t, %1; cvt.u32.u64 %0, t; }" : "=r"(a) : "l"(p));
    return a;
}
__device__ __forceinline__ void ldsm_x4(uint32_t* r, uint32_t addr) {
    asm volatile("ldmatrix.sync.aligned.m8n8.x4.shared.b16 {%0,%1,%2,%3}, [%4];"
                 : "=r"(r[0]), "=r"(r[1]), "=r"(r[2]), "=r"(r[3]) : "r"(addr));
}
__device__ __forceinline__ void ldsm_x2(uint32_t* r, uint32_t addr) {
    asm volatile("ldmatrix.sync.aligned.m8n8.x2.shared.b16 {%0,%1}, [%2];"
                 : "=r"(r[0]), "=r"(r[1]) : "r"(addr));
}
__device__ __forceinline__ void mma_bf16(float* c, const uint32_t* a, const uint32_t* b) {
    asm volatile("mma.sync.aligned.m16n8k16.row.col.f32.bf16.bf16.f32 "
                 "{%0,%1,%2,%3}, {%4,%5,%6,%7}, {%8,%9}, {%0,%1,%2,%3};"
                 : "+f"(c[0]), "+f"(c[1]), "+f"(c[2]), "+f"(c[3])
                 : "r"(a[0]), "r"(a[1]), "r"(a[2]), "r"(a[3]), "r"(b[0]), "r"(b[1]));
}
__device__ __forceinline__ uint32_t pack2(float x0, float x1, float& r0, float& r1) {
    __nv_bfloat16 h0 = __float2bfloat16_rn(x0);
    __nv_bfloat16 h1 = __float2bfloat16_rn(x1);
    r0 = x0 - __bfloat162float(h0);
    r1 = x1 - __bfloat162float(h1);
    return ((uint32_t)__bfloat16_as_ushort(h1) << 16) | (uint32_t)__bfloat16_as_ushort(h0);
}
__device__ __forceinline__ uint32_t pack2lo(float r0, float r1) {
    __nv_bfloat16 l0 = __float2bfloat16_rn(r0);
    __nv_bfloat16 l1 = __float2bfloat16_rn(r1);
    return ((uint32_t)__bfloat16_as_ushort(l1) << 16) | (uint32_t)__bfloat16_as_ushort(l0);
}

// ---------------- weight transpose + hi/lo split: WT[n][k] = W[k][n] ----------------
__global__ void wconv_kernel(const float* __restrict__ W, __nv_bfloat16* __restrict__ Th,
                             __nv_bfloat16* __restrict__ Tl, int K, int NC, int Kp, int NCp) {
    int idx = blockIdx.x * 256 + threadIdx.x;
    if (idx >= NCp * Kp) return;
    int n = idx / Kp, k = idx % Kp;
    float x = (n < NC && k < K) ? W[(size_t)k * NC + n] : 0.0f;
    __nv_bfloat16 h = __float2bfloat16_rn(x);
    Th[idx] = h;
    Tl[idx] = __float2bfloat16_rn(x - __bfloat162float(h));
}

// ---------------- mma.sync split-bf16 GEMM with fused epilogue ----------------
// C[M,NC] = epi(A[M,K] @ B), B given transposed bf16 hi/lo [NCp, Kp]
// mode 0: relu(x+bias) | mode 1: BN(x+bias) | mode 2: relu(BN(x+bias))
__global__ void __launch_bounds__(256, 2)
gemm_mma_kernel(const float* __restrict__ A,
                const __nv_bfloat16* __restrict__ BTh, const __nv_bfloat16* __restrict__ BTl,
                const float* __restrict__ bias, float* __restrict__ C,
                int M, int K, int Kp, int NC, int mode,
                const float* __restrict__ bn_g, const float* __restrict__ bn_b,
                const float* __restrict__ bn_m, const float* __restrict__ bn_v) {
    __shared__ __align__(16) uint16_t sAh[BM * LDK];
    __shared__ __align__(16) uint16_t sAl[BM * LDK];
    __shared__ __align__(16) uint16_t sBh[BN * LDK];
    __shared__ __align__(16) uint16_t sBl[BN * LDK];

    const int tid = threadIdx.x;
    const int wid = tid >> 5;
    const int lane = tid & 31;
    const int warp_m = wid >> 2;          // 0..1  (64 rows each)
    const int warp_n = wid & 3;           // 0..3  (32 cols each)
    const int row_base = blockIdx.y * BM;
    const int col_base = blockIdx.x * BN;

    // ldmatrix per-thread byte offsets within a tile
    const uint32_t aoff = ((uint32_t)((lane & 15) * LDK + ((lane & 16) ? 8 : 0))) * 2;
    const uint32_t boff = ((uint32_t)((lane & 7) * LDK + ((lane & 8) ? 8 : 0))) * 2;
    const uint32_t uAh = smem_u32(sAh), uAl = smem_u32(sAl);
    const uint32_t uBh = smem_u32(sBh), uBl = smem_u32(sBl);

    float acc[16][4];
#pragma unroll
    for (int i = 0; i < 16; i++)
#pragma unroll
        for (int j = 0; j < 4; j++) acc[i][j] = 0.0f;

    const int nchunks = Kp / BK;
    for (int ch = 0; ch < nchunks; ch++) {
        const int k0 = ch * BK;
        // stage A chunk [128 x 32] fp32 -> bf16 hi/lo (pairs of 2 k)
#pragma unroll
        for (int i = 0; i < 8; i++) {
            int p = i * 256 + tid;        // 2048 pairs
            int m = p >> 4, kp = p & 15;
            int gr = row_base + m;
            int k = k0 + kp * 2;
            float x0 = 0.0f, x1 = 0.0f;
            if (gr < M) {
                const float* ar = A + (size_t)gr * K;
                if (k < K) x0 = ar[k];
                if (k + 1 < K) x1 = ar[k + 1];
            }
            float r0, r1;
            uint32_t hp = pack2(x0, x1, r0, r1);
            uint32_t lp = pack2lo(r0, r1);
            int hw = m * LDK + kp * 2;    // even halfword index
            *(uint32_t*)(sAh + hw) = hp;
            *(uint32_t*)(sAl + hw) = lp;
        }
        // stage B chunk [128 x 32] bf16 hi/lo (pre-transposed, padded)
#pragma unroll
        for (int i = 0; i < 8; i++) {
            int p = i * 256 + tid;
            int n = p >> 4, kp = p & 15;
            size_t goff = (size_t)(col_base + n) * Kp + k0 + kp * 2;
            uint32_t hp = *(const uint32_t*)(BTh + goff);
            uint32_t lp = *(const uint32_t*)(BTl + goff);
            int hw = n * LDK + kp * 2;
            *(uint32_t*)(sBh + hw) = hp;
            *(uint32_t*)(sBl + hw) = lp;
        }
        __syncthreads();

        // 3 terms: AhBh, AhBl, AlBh
#pragma unroll
        for (int t = 0; t < 3; t++) {
            const uint32_t abase = (t == 2 ? uAl : uAh) + aoff;
            const uint32_t bbase = (t == 1 ? uBl : uBh) + boff;
#pragma unroll
            for (int ks = 0; ks < BK / 16; ks++) {
                uint32_t af[4][4], bf[4][2];
#pragma unroll
                for (int tm = 0; tm < 4; tm++)
                    ldsm_x4(af[tm], abase +
                            (uint32_t)(((warp_m * 64 + tm * 16) * LDK + ks * 16) * 2));
#pragma unroll
                for (int tn = 0; tn < 4; tn++)
                    ldsm_x2(bf[tn], bbase +
                            (uint32_t)(((warp_n * 32 + tn * 8) * LDK + ks * 16) * 2));
#pragma unroll
                for (int tm = 0; tm < 4; tm++)
#pragma unroll
                    for (int tn = 0; tn < 4; tn++)
                        mma_bf16(acc[tm * 4 + tn], af[tm], bf[tn]);
            }
        }
        __syncthreads();
    }

    // epilogue: frag layout c0,c1 -> row lane/4, cols (lane%4)*2+{0,1}; c2,c3 -> row+8
    const int r_base = row_base + warp_m * 64;
    const int c_base = col_base + warp_n * 32;
#pragma unroll
    for (int tn = 0; tn < 4; tn++) {
        int c = c_base + tn * 8 + (lane & 3) * 2;
        if (c >= NC) continue;
        float bia0 = bias[c], bia1 = bias[c + 1];
        float sc0 = 1.0f, sc1 = 1.0f, mn0 = 0.0f, mn1 = 0.0f, bb0 = 0.0f, bb1 = 0.0f;
        if (mode >= 1) {
            sc0 = bn_g[c] * rsqrtf(bn_v[c] + BN_EPS);
            sc1 = bn_g[c + 1] * rsqrtf(bn_v[c + 1] + BN_EPS);
            mn0 = bn_m[c]; mn1 = bn_m[c + 1];
            bb0 = bn_b[c]; bb1 = bn_b[c + 1];
        }
#pragma unroll
        for (int tm = 0; tm < 4; tm++) {
            const float* a4 = acc[tm * 4 + tn];
            int r0 = r_base + tm * 16 + (lane >> 2);
#pragma unroll
            for (int half = 0; half < 2; half++) {
                int r = r0 + half * 8;
                if (r >= M) continue;
                float x0 = a4[half * 2 + 0] + bia0;
                float x1 = a4[half * 2 + 1] + bia1;
                if (mode == 0) {
                    x0 = fmaxf(x0, 0.0f); x1 = fmaxf(x1, 0.0f);
                } else {
                    x0 = (x0 - mn0) * sc0 + bb0;
                    x1 = (x1 - mn1) * sc1 + bb1;
                    if (mode == 2) { x0 = fmaxf(x0, 0.0f); x1 = fmaxf(x1, 0.0f); }
                }
                *(float2*)(C + (size_t)r * NC + c) = make_float2(x0, x1);
            }
        }
    }
}

// ---------------- graph kernels ----------------
__global__ void node_init_kernel(const int* __restrict__ an, const int* __restrict__ ct,
                                 const float* __restrict__ ne0, const float* __restrict__ ne1,
                                 float* __restrict__ h, int N) {
    int i = blockIdx.x * 8 + (threadIdx.x >> 5);
    if (i >= N) return;
    int lane = threadIdx.x & 31;
    const float* p0 = ne0 + (size_t)an[i] * D;
    const float* p1 = ne1 + (size_t)ct[i] * D;
    float* out = h + (size_t)i * D;
    for (int d = lane; d < D; d += 32)
        out[d] = p0[d] + p1[d];
}

__global__ void edge_message_kernel(const float* __restrict__ h,
                                    const float* __restrict__ ee0, const float* __restrict__ ee1,
                                    const int* __restrict__ bt, const int* __restrict__ bd,
                                    const int* __restrict__ src, const int* __restrict__ dst,
                                    float* __restrict__ agg, int E) {
    int e = blockIdx.x * 8 + (threadIdx.x >> 5);
    if (e >= E) return;
    int lane = threadIdx.x & 31;
    const float* p0 = ee0 + (size_t)bt[e] * D;
    const float* p1 = ee1 + (size_t)bd[e] * D;
    const float* hs = h + (size_t)src[e] * D;
    float* out = agg + (size_t)dst[e] * D;
    for (int d = lane; d < D; d += 32)
        atomicAdd(&out[d], hs[d] + p0[d] + p1[d]);
}

__global__ void pool_kernel(const float* __restrict__ h, const int* __restrict__ gid,
                            float* __restrict__ gsum, float* __restrict__ cnt, int N) {
    int i = blockIdx.x * 8 + (threadIdx.x >> 5);
    if (i >= N) return;
    int lane = threadIdx.x & 31;
    int g = gid[i];
    const float* hr = h + (size_t)i * D;
    float* out = gsum + (size_t)g * D;
    for (int d = lane; d < D; d += 32)
        atomicAdd(&out[d], hr[d]);
    if (lane == 0)
        atomicAdd(&cnt[g], 1.0f);
}

__global__ void head_kernel(const float* __restrict__ gsum, const float* __restrict__ cnt,
                            const float* __restrict__ Wd, const float* __restrict__ bd,
                            float* __restrict__ out, int G) {
    __shared__ float row[D];
    int g = blockIdx.x;
    if (g >= G) return;
    float inv = 1.0f / fmaxf(cnt[g], 1.0f);
    for (int k = threadIdx.x; k < D; k += blockDim.x)
        row[k] = gsum[(size_t)g * D + k] * inv;
    __syncthreads();
    int c = threadIdx.x;
    float acc = bd[c];
#pragma unroll 4
    for (int k = 0; k < D; k++)
        acc = fmaf(row[k], Wd[(size_t)k * 256 + c], acc);
    out[(size_t)g * 256 + c] = acc;
}

// ---------------- launch ----------------
extern "C" void kernel_launch(void* const* d_in, const int* in_sizes, int n_in,
                              void* d_out, int out_size) {
    const int*   atomic_number = (const int*)d_in[0];
    const int*   chirality     = (const int*)d_in[1];
    const int*   bond_type     = (const int*)d_in[2];
    const int*   bond_dir      = (const int*)d_in[3];
    const int*   src           = (const int*)d_in[4];
    const int*   dst           = (const int*)d_in[5];
    const int*   gid           = (const int*)d_in[6];
    const float* ne0           = (const float*)d_in[8];
    const float* ne1           = (const float*)d_in[9];
    const float* ee0           = (const float*)d_in[10];
    const float* ee1           = (const float*)d_in[11];
    const float* W1            = (const float*)d_in[12];
    const float* b1            = (const float*)d_in[13];
    const float* W2            = (const float*)d_in[14];
    const float* b2            = (const float*)d_in[15];
    const float* gamma         = (const float*)d_in[16];
    const float* beta          = (const float*)d_in[17];
    const float* mean          = (const float*)d_in[18];
    const float* var           = (const float*)d_in[19];
    const float* Wd            = (const float*)d_in[20];
    const float* bd            = (const float*)d_in[21];
    float* out = (float*)d_out;

    int N = in_sizes[0];
    int E = in_sizes[2];
    int G = out_size / 256;
    if (N > MAXN) N = MAXN;
    if (G > MAXG) G = MAXG;

    float *h_ptr, *agg_ptr, *t_ptr, *gsum_ptr, *cnt_ptr;
    __nv_bfloat16 *w1h, *w1l, *w2h, *w2l;
    cudaGetSymbolAddress((void**)&h_ptr, g_h);
    cudaGetSymbolAddress((void**)&agg_ptr, g_agg);
    cudaGetSymbolAddress((void**)&t_ptr, g_t);
    cudaGetSymbolAddress((void**)&gsum_ptr, g_gsum);
    cudaGetSymbolAddress((void**)&cnt_ptr, g_cnt);
    cudaGetSymbolAddress((void**)&w1h, g_w1h);
    cudaGetSymbolAddress((void**)&w1l, g_w1l);
    cudaGetSymbolAddress((void**)&w2h, g_w2h);
    cudaGetSymbolAddress((void**)&w2l, g_w2l);

    // pre-transpose + hi/lo split all layer weights
    for (int l = 0; l < LAYERS; l++) {
        wconv_kernel<<<(N1P * K1P + 255) / 256, 256>>>(
            W1 + (size_t)l * D * D2, w1h + (size_t)l * N1P * K1P, w1l + (size_t)l * N1P * K1P,
            D, D2, K1P, N1P);
        wconv_kernel<<<(N2P * K2P + 255) / 256, 256>>>(
            W2 + (size_t)l * D2 * D, w2h + (size_t)l * N2P * K2P, w2l + (size_t)l * N2P * K2P,
            D2, D, K2P, N2P);
    }

    node_init_kernel<<<(N + 7) / 8, 256>>>(atomic_number, chirality, ne0, ne1, h_ptr, N);

    int nrb = (N + BM - 1) / BM;
    for (int l = 0; l < LAYERS; l++) {
        cudaMemsetAsync(agg_ptr, 0, (size_t)N * D * sizeof(float));
        edge_message_kernel<<<(E + 7) / 8, 256>>>(h_ptr,
                                                  ee0 + (size_t)l * 6 * D,
                                                  ee1 + (size_t)l * 3 * D,
                                                  bond_type, bond_dir, src, dst, agg_ptr, E);
        // GEMM1: t = relu(agg @ W1[l] + b1[l])   [N,300]x[300,600]
        {
            dim3 grid(N1P / BN, nrb);
            gemm_mma_kernel<<<grid, 256>>>(
                agg_ptr, w1h + (size_t)l * N1P * K1P, w1l + (size_t)l * N1P * K1P,
                b1 + (size_t)l * D2, t_ptr, N, D, K1P, D2, /*mode=*/0,
                nullptr, nullptr, nullptr, nullptr);
        }
        // GEMM2: h = [relu](BN(t @ W2[l] + b2[l]))   [N,600]x[600,300]
        {
            dim3 grid(N2P / BN, nrb);
            int mode = (l < LAYERS - 1) ? 2 : 1;
            gemm_mma_kernel<<<grid, 256>>>(
                t_ptr, w2h + (size_t)l * N2P * K2P, w2l + (size_t)l * N2P * K2P,
                b2 + (size_t)l * D, h_ptr, N, D2, K2P, D, mode,
                gamma + (size_t)l * D, beta + (size_t)l * D,
                mean + (size_t)l * D, var + (size_t)l * D);
        }
    }

    cudaMemsetAsync(gsum_ptr, 0, (size_t)G * D * sizeof(float));
    cudaMemsetAsync(cnt_ptr, 0, (size_t)G * sizeof(float));
    pool_kernel<<<(N + 7) / 8, 256>>>(h_ptr, gid, gsum_ptr, cnt_ptr, N);
    head_kernel<<<G, 256>>>(gsum_ptr, cnt_ptr, Wd, bd, out, G);
}

// round 10
// speedup vs baseline: 3.4678x; 1.5228x over previous
#include <cuda_runtime.h>
#include <cuda_bf16.h>
#include <math.h>
#include <stdint.h>

#define D 300
#define D2 600
#define LAYERS 5
#define MAXN 200000
#define MAXG 1024
#define BN_EPS 1e-5f

// ---- GEMM tiling ----
#define BM 64
#define BN 128
#define BK 32
#define LDK 40            // halfwords per smem row (80B): conflict-free ldmatrix + 16B aligned
#define K1P 320           // GEMM1 K=300 padded
#define K2P 640           // GEMM2 K=600 padded (= t row stride)
#define N1P 640           // GEMM1 NC=600 padded (5 col tiles of 128)
#define N2P 384           // GEMM2 NC=300 padded (3 col tiles of 128)
#define ROWPAD 64

#define STG_A   (BM * LDK * 2)            // 5120 B per A half
#define STG_AB  (2 * STG_A)               // 10240
#define STG_B   (BN * LDK * 2)            // 10240 B per B half
#define STAGE_BYTES (STG_AB + 2 * STG_B)  // 30720
#define NSTAGES 3
#define GEMM_SMEM (NSTAGES * STAGE_BYTES) // 92160

// ---------------- scratch (static device globals, zero-init .bss) ----------------
__device__ float g_h[(size_t)(MAXN + ROWPAD) * D];
__device__ float g_agg[(size_t)MAXN * D];
__device__ float g_gsum[(size_t)MAXG * D];
__device__ float g_cnt[MAXG];
__device__ __nv_bfloat16 g_ah[(size_t)(MAXN + ROWPAD) * K1P];   // split agg (GEMM1 A)
__device__ __nv_bfloat16 g_al[(size_t)(MAXN + ROWPAD) * K1P];
__device__ __nv_bfloat16 g_th[(size_t)(MAXN + ROWPAD) * K2P];   // split t (GEMM2 A)
__device__ __nv_bfloat16 g_tl[(size_t)(MAXN + ROWPAD) * K2P];
__device__ __nv_bfloat16 g_w1h[(size_t)LAYERS * N1P * K1P];
__device__ __nv_bfloat16 g_w1l[(size_t)LAYERS * N1P * K1P];
__device__ __nv_bfloat16 g_w2h[(size_t)LAYERS * N2P * K2P];
__device__ __nv_bfloat16 g_w2l[(size_t)LAYERS * N2P * K2P];

// ---------------- helpers ----------------
__device__ __forceinline__ uint32_t smem_u32(const void* p) {
    uint32_t a;
    asm("{ .reg .u64 t; cvta.to.shared.u64 t, %1; cvt.u32.u64 %0, t; }" : "=r"(a) : "l"(p));
    return a;
}
__device__ __forceinline__ void cp16(uint32_t dst, const void* src) {
    asm volatile("cp.async.cg.shared.global [%0], [%1], 16;" :: "r"(dst), "l"(src));
}
#define CP_COMMIT() asm volatile("cp.async.commit_group;" ::: "memory")
#define CP_WAIT1()  asm volatile("cp.async.wait_group 1;" ::: "memory")
__device__ __forceinline__ void ldsm_x4(uint32_t* r, uint32_t addr) {
    asm volatile("ldmatrix.sync.aligned.m8n8.x4.shared.b16 {%0,%1,%2,%3}, [%4];"
                 : "=r"(r[0]), "=r"(r[1]), "=r"(r[2]), "=r"(r[3]) : "r"(addr));
}
__device__ __forceinline__ void ldsm_x2(uint32_t* r, uint32_t addr) {
    asm volatile("ldmatrix.sync.aligned.m8n8.x2.shared.b16 {%0,%1}, [%2];"
                 : "=r"(r[0]), "=r"(r[1]) : "r"(addr));
}
__device__ __forceinline__ void mma_bf16(float* c, const uint32_t* a, const uint32_t* b) {
    asm volatile("mma.sync.aligned.m16n8k16.row.col.f32.bf16.bf16.f32 "
                 "{%0,%1,%2,%3}, {%4,%5,%6,%7}, {%8,%9}, {%0,%1,%2,%3};"
                 : "+f"(c[0]), "+f"(c[1]), "+f"(c[2]), "+f"(c[3])
                 : "r"(a[0]), "r"(a[1]), "r"(a[2]), "r"(a[3]), "r"(b[0]), "r"(b[1]));
}
__device__ __forceinline__ uint32_t pack2(float x0, float x1, float& r0, float& r1) {
    __nv_bfloat16 h0 = __float2bfloat16_rn(x0);
    __nv_bfloat16 h1 = __float2bfloat16_rn(x1);
    r0 = x0 - __bfloat162float(h0);
    r1 = x1 - __bfloat162float(h1);
    return ((uint32_t)__bfloat16_as_ushort(h1) << 16) | (uint32_t)__bfloat16_as_ushort(h0);
}
__device__ __forceinline__ uint32_t pack2lo(float r0, float r1) {
    __nv_bfloat16 l0 = __float2bfloat16_rn(r0);
    __nv_bfloat16 l1 = __float2bfloat16_rn(r1);
    return ((uint32_t)__bfloat16_as_ushort(l1) << 16) | (uint32_t)__bfloat16_as_ushort(l0);
}

// ---------------- weight transpose + hi/lo split: WT[n][k] = W[k][n] ----------------
__global__ void wconv_kernel(const float* __restrict__ W, __nv_bfloat16* __restrict__ Th,
                             __nv_bfloat16* __restrict__ Tl, int K, int NC, int Kp, int NCp) {
    int idx = blockIdx.x * 256 + threadIdx.x;
    if (idx >= NCp * Kp) return;
    int n = idx / Kp, k = idx % Kp;
    float x = (n < NC && k < K) ? W[(size_t)k * NC + n] : 0.0f;
    __nv_bfloat16 h = __float2bfloat16_rn(x);
    Th[idx] = h;
    Tl[idx] = __float2bfloat16_rn(x - __bfloat162float(h));
}

// ---------------- agg fp32 -> split bf16 hi/lo, K-padded ----------------
__global__ void aconv_kernel(const float* __restrict__ A, __nv_bfloat16* __restrict__ Ah,
                             __nv_bfloat16* __restrict__ Al, int N) {
    int idx = blockIdx.x * 256 + threadIdx.x;
    const int PPR = K1P / 2;   // 160 uint32 per row
    if (idx >= N * PPR) return;
    int r = idx / PPR, kp = idx - r * PPR;
    int k = kp * 2;
    const float* ar = A + (size_t)r * D;
    float x0 = (k < D) ? ar[k] : 0.0f;
    float x1 = (k + 1 < D) ? ar[k + 1] : 0.0f;
    float r0, r1;
    uint32_t hp = pack2(x0, x1, r0, r1);
    uint32_t lp = pack2lo(r0, r1);
    ((uint32_t*)Ah)[(size_t)r * PPR + kp] = hp;
    ((uint32_t*)Al)[(size_t)r * PPR + kp] = lp;
}

// ---------------- pipelined split-bf16 mma.sync GEMM ----------------
// acc = A[M,Kp] @ B^T  (A,B pre-split bf16 hi/lo, K-padded; 3 terms AhBh+AhBl+AlBh)
// output: if Th: t split-store relu(x+bias) to Th/Tl (stride K2P halfwords)
//         else : Cf fp32, mode 1 BN(x+bias), mode 2 relu(BN(..))
__global__ void __launch_bounds__(256, 2)
gemm_pipe_kernel(const __nv_bfloat16* __restrict__ Ah, const __nv_bfloat16* __restrict__ Al,
                 const __nv_bfloat16* __restrict__ Bh, const __nv_bfloat16* __restrict__ Bl,
                 const float* __restrict__ bias,
                 __nv_bfloat16* __restrict__ Th, __nv_bfloat16* __restrict__ Tl,
                 float* __restrict__ Cf,
                 int M, int Kp, int NC, int mode,
                 const float* __restrict__ bn_g, const float* __restrict__ bn_b,
                 const float* __restrict__ bn_m, const float* __restrict__ bn_v) {
    extern __shared__ __align__(16) char dsm[];
    const uint32_t sb = smem_u32(dsm);
    const int tid = threadIdx.x;
    const int wid = tid >> 5;
    const int lane = tid & 31;
    const int warp_m = wid >> 2;          // 0..1 (32 rows each)
    const int warp_n = wid & 3;           // 0..3 (32 cols each)
    const int row_base = blockIdx.y * BM;
    const int col_base = blockIdx.x * BN;
    const int nch = Kp / BK;

    // per-thread ldmatrix lane offsets (bytes)
    const uint32_t a_lane = ((uint32_t)((lane & 15) * LDK + ((lane & 16) ? 8 : 0))) * 2;
    const uint32_t b_lane = ((uint32_t)((lane & 7) * LDK + ((lane & 8) ? 8 : 0))) * 2;

    float acc[8][4];
#pragma unroll
    for (int i = 0; i < 8; i++)
#pragma unroll
        for (int j = 0; j < 4; j++) acc[i][j] = 0.0f;

    // ---- stage loader: 1536 x 16B chunks, 6 per thread ----
    auto load_stage = [&](int stg, int k0) {
        uint32_t base = sb + stg * STAGE_BYTES;
#pragma unroll
        for (int j = 0; j < 6; j++) {
            int id = j * 256 + tid;
            uint32_t dst;
            const __nv_bfloat16* src;
            if (id < 512) {                       // A: 64 rows x 4 chunks x 2 halves
                int half = id >> 8;
                int q = id & 255;
                int r = q >> 2, c = q & 3;
                dst = base + half * STG_A + (uint32_t)(r * 80 + c * 16);
                src = (half ? Al : Ah) + (size_t)(row_base + r) * Kp + k0 + c * 8;
            } else {                              // B: 128 rows x 4 chunks x 2 halves
                int id2 = id - 512;
                int half = id2 >> 9;
                int q = id2 & 511;
                int r = q >> 2, c = q & 3;
                dst = base + STG_AB + half * STG_B + (uint32_t)(r * 80 + c * 16);
                src = (half ? Bl : Bh) + (size_t)(col_base + r) * Kp + k0 + c * 8;
            }
            cp16(dst, src);
        }
    };

    load_stage(0, 0);
    CP_COMMIT();
    load_stage(1, BK);
    CP_COMMIT();

    for (int ch = 0; ch < nch; ch++) {
        CP_WAIT1();
        __syncthreads();
        if (ch + 2 < nch) load_stage((ch + 2) % NSTAGES, (ch + 2) * BK);
        CP_COMMIT();

        const uint32_t ah = sb + (ch % NSTAGES) * STAGE_BYTES;
        const uint32_t al = ah + STG_A;
        const uint32_t bh = ah + STG_AB;
        const uint32_t bl = bh + STG_B;
#pragma unroll
        for (int ks = 0; ks < 2; ks++) {
            uint32_t af_h[2][4], af_l[2][4], bf_h[4][2], bf_l[4][2];
#pragma unroll
            for (int tm = 0; tm < 2; tm++) {
                uint32_t toff = (uint32_t)(((warp_m * 32 + tm * 16) * LDK + ks * 16) * 2) + a_lane;
                ldsm_x4(af_h[tm], ah + toff);
                ldsm_x4(af_l[tm], al + toff);
            }
#pragma unroll
            for (int tn = 0; tn < 4; tn++) {
                uint32_t toff = (uint32_t)(((warp_n * 32 + tn * 8) * LDK + ks * 16) * 2) + b_lane;
                ldsm_x2(bf_h[tn], bh + toff);
                ldsm_x2(bf_l[tn], bl + toff);
            }
#pragma unroll
            for (int tm = 0; tm < 2; tm++)
#pragma unroll
                for (int tn = 0; tn < 4; tn++) {
                    mma_bf16(acc[tm * 4 + tn], af_h[tm], bf_h[tn]);
                    mma_bf16(acc[tm * 4 + tn], af_h[tm], bf_l[tn]);
                    mma_bf16(acc[tm * 4 + tn], af_l[tm], bf_h[tn]);
                }
        }
        __syncthreads();
    }

    // ---- epilogue ----
    const int r_base = row_base + warp_m * 32 + (lane >> 2);
    const int c_base2 = col_base + warp_n * 32 + (lane & 3) * 2;
#pragma unroll
    for (int tn = 0; tn < 4; tn++) {
        int c = c_base2 + tn * 8;
        if (c >= NC) continue;
        float bia0 = bias[c], bia1 = bias[c + 1];
        float sc0 = 0, sc1 = 0, mn0 = 0, mn1 = 0, bb0 = 0, bb1 = 0;
        if (!Th) {
            sc0 = bn_g[c] * rsqrtf(bn_v[c] + BN_EPS);
            sc1 = bn_g[c + 1] * rsqrtf(bn_v[c + 1] + BN_EPS);
            mn0 = bn_m[c]; mn1 = bn_m[c + 1];
            bb0 = bn_b[c]; bb1 = bn_b[c + 1];
        }
#pragma unroll
        for (int tm = 0; tm < 2; tm++) {
            const float* a4 = acc[tm * 4 + tn];
#pragma unroll
            for (int half = 0; half < 2; half++) {
                int r = r_base + tm * 16 + half * 8;
                if (r >= M) continue;
                float x0 = a4[half * 2 + 0] + bia0;
                float x1 = a4[half * 2 + 1] + bia1;
                if (Th) {
                    // GEMM1: relu then split-store bf16 hi/lo
                    x0 = fmaxf(x0, 0.0f); x1 = fmaxf(x1, 0.0f);
                    float r0, r1;
                    uint32_t hp = pack2(x0, x1, r0, r1);
                    uint32_t lp = pack2lo(r0, r1);
                    size_t off = (size_t)r * K2P + c;
                    *(uint32_t*)(Th + off) = hp;
                    *(uint32_t*)(Tl + off) = lp;
                } else {
                    x0 = (x0 - mn0) * sc0 + bb0;
                    x1 = (x1 - mn1) * sc1 + bb1;
                    if (mode == 2) { x0 = fmaxf(x0, 0.0f); x1 = fmaxf(x1, 0.0f); }
                    *(float2*)(Cf + (size_t)r * NC + c) = make_float2(x0, x1);
                }
            }
        }
    }
}

// ---------------- graph kernels ----------------
__global__ void node_init_kernel(const int* __restrict__ an, const int* __restrict__ ct,
                                 const float* __restrict__ ne0, const float* __restrict__ ne1,
                                 float* __restrict__ h, int N) {
    int i = blockIdx.x * 8 + (threadIdx.x >> 5);
    if (i >= N) return;
    int lane = threadIdx.x & 31;
    const float* p0 = ne0 + (size_t)an[i] * D;
    const float* p1 = ne1 + (size_t)ct[i] * D;
    float* out = h + (size_t)i * D;
    for (int d = lane; d < D; d += 32)
        out[d] = p0[d] + p1[d];
}

__global__ void edge_message_kernel(const float* __restrict__ h,
                                    const float* __restrict__ ee0, const float* __restrict__ ee1,
                                    const int* __restrict__ bt, const int* __restrict__ bd,
                                    const int* __restrict__ src, const int* __restrict__ dst,
                                    float* __restrict__ agg, int E) {
    int e = blockIdx.x * 8 + (threadIdx.x >> 5);
    if (e >= E) return;
    int lane = threadIdx.x & 31;
    const float* p0 = ee0 + (size_t)bt[e] * D;
    const float* p1 = ee1 + (size_t)bd[e] * D;
    const float* hs = h + (size_t)src[e] * D;
    float* out = agg + (size_t)dst[e] * D;
    for (int d = lane; d < D; d += 32)
        atomicAdd(&out[d], hs[d] + p0[d] + p1[d]);
}

__global__ void pool_kernel(const float* __restrict__ h, const int* __restrict__ gid,
                            float* __restrict__ gsum, float* __restrict__ cnt, int N) {
    int i = blockIdx.x * 8 + (threadIdx.x >> 5);
    if (i >= N) return;
    int lane = threadIdx.x & 31;
    int g = gid[i];
    const float* hr = h + (size_t)i * D;
    float* out = gsum + (size_t)g * D;
    for (int d = lane; d < D; d += 32)
        atomicAdd(&out[d], hr[d]);
    if (lane == 0)
        atomicAdd(&cnt[g], 1.0f);
}

__global__ void head_kernel(const float* __restrict__ gsum, const float* __restrict__ cnt,
                            const float* __restrict__ Wd, const float* __restrict__ bd,
                            float* __restrict__ out, int G) {
    __shared__ float row[D];
    int g = blockIdx.x;
    if (g >= G) return;
    float inv = 1.0f / fmaxf(cnt[g], 1.0f);
    for (int k = threadIdx.x; k < D; k += blockDim.x)
        row[k] = gsum[(size_t)g * D + k] * inv;
    __syncthreads();
    int c = threadIdx.x;
    float acc = bd[c];
#pragma unroll 4
    for (int k = 0; k < D; k++)
        acc = fmaf(row[k], Wd[(size_t)k * 256 + c], acc);
    out[(size_t)g * 256 + c] = acc;
}

// ---------------- launch ----------------
extern "C" void kernel_launch(void* const* d_in, const int* in_sizes, int n_in,
                              void* d_out, int out_size) {
    const int*   atomic_number = (const int*)d_in[0];
    const int*   chirality     = (const int*)d_in[1];
    const int*   bond_type     = (const int*)d_in[2];
    const int*   bond_dir      = (const int*)d_in[3];
    const int*   src           = (const int*)d_in[4];
    const int*   dst           = (const int*)d_in[5];
    const int*   gid           = (const int*)d_in[6];
    const float* ne0           = (const float*)d_in[8];
    const float* ne1           = (const float*)d_in[9];
    const float* ee0           = (const float*)d_in[10];
    const float* ee1           = (const float*)d_in[11];
    const float* W1            = (const float*)d_in[12];
    const float* b1            = (const float*)d_in[13];
    const float* W2            = (const float*)d_in[14];
    const float* b2            = (const float*)d_in[15];
    const float* gamma         = (const float*)d_in[16];
    const float* beta          = (const float*)d_in[17];
    const float* mean          = (const float*)d_in[18];
    const float* var           = (const float*)d_in[19];
    const float* Wd            = (const float*)d_in[20];
    const float* bd            = (const float*)d_in[21];
    float* out = (float*)d_out;

    int N = in_sizes[0];
    int E = in_sizes[2];
    int G = out_size / 256;
    if (N > MAXN) N = MAXN;
    if (G > MAXG) G = MAXG;

    static int attr_set = 0;
    if (!attr_set) {
        cudaFuncSetAttribute(gemm_pipe_kernel, cudaFuncAttributeMaxDynamicSharedMemorySize, GEMM_SMEM);
        attr_set = 1;
    }

    float *h_ptr, *agg_ptr, *gsum_ptr, *cnt_ptr;
    __nv_bfloat16 *ah, *al, *th, *tl, *w1h, *w1l, *w2h, *w2l;
    cudaGetSymbolAddress((void**)&h_ptr, g_h);
    cudaGetSymbolAddress((void**)&agg_ptr, g_agg);
    cudaGetSymbolAddress((void**)&gsum_ptr, g_gsum);
    cudaGetSymbolAddress((void**)&cnt_ptr, g_cnt);
    cudaGetSymbolAddress((void**)&ah, g_ah);
    cudaGetSymbolAddress((void**)&al, g_al);
    cudaGetSymbolAddress((void**)&th, g_th);
    cudaGetSymbolAddress((void**)&tl, g_tl);
    cudaGetSymbolAddress((void**)&w1h, g_w1h);
    cudaGetSymbolAddress((void**)&w1l, g_w1l);
    cudaGetSymbolAddress((void**)&w2h, g_w2h);
    cudaGetSymbolAddress((void**)&w2l, g_w2l);

    for (int l = 0; l < LAYERS; l++) {
        wconv_kernel<<<(N1P * K1P + 255) / 256, 256>>>(
            W1 + (size_t)l * D * D2, w1h + (size_t)l * N1P * K1P, w1l + (size_t)l * N1P * K1P,
            D, D2, K1P, N1P);
        wconv_kernel<<<(N2P * K2P + 255) / 256, 256>>>(
            W2 + (size_t)l * D2 * D, w2h + (size_t)l * N2P * K2P, w2l + (size_t)l * N2P * K2P,
            D2, D, K2P, N2P);
    }

    node_init_kernel<<<(N + 7) / 8, 256>>>(atomic_number, chirality, ne0, ne1, h_ptr, N);

    const int nrb = (N + BM - 1) / BM;
    for (int l = 0; l < LAYERS; l++) {
        cudaMemsetAsync(agg_ptr, 0, (size_t)N * D * sizeof(float));
        edge_message_kernel<<<(E + 7) / 8, 256>>>(h_ptr,
                                                  ee0 + (size_t)l * 6 * D,
                                                  ee1 + (size_t)l * 3 * D,
                                                  bond_type, bond_dir, src, dst, agg_ptr, E);
        // split agg -> bf16 hi/lo (K padded to 320)
        aconv_kernel<<<(N * (K1P / 2) + 255) / 256, 256>>>(agg_ptr, ah, al, N);
        // GEMM1: t = relu(agg @ W1 + b1), split-stored
        {
            dim3 grid(N1P / BN, nrb);
            gemm_pipe_kernel<<<grid, 256, GEMM_SMEM>>>(
                ah, al, w1h + (size_t)l * N1P * K1P, w1l + (size_t)l * N1P * K1P,
                b1 + (size_t)l * D2, th, tl, nullptr,
                N, K1P, D2, 0, nullptr, nullptr, nullptr, nullptr);
        }
        // GEMM2: h = [relu](BN(t @ W2 + b2))
        {
            dim3 grid(N2P / BN, nrb);
            int mode = (l < LAYERS - 1) ? 2 : 1;
            gemm_pipe_kernel<<<grid, 256, GEMM_SMEM>>>(
                th, tl, w2h + (size_t)l * N2P * K2P, w2l + (size_t)l * N2P * K2P,
                b2 + (size_t)l * D, nullptr, nullptr, h_ptr,
                N, K2P, D, mode,
                gamma + (size_t)l * D, beta + (size_t)l * D,
                mean + (size_t)l * D, var + (size_t)l * D);
        }
    }

    cudaMemsetAsync(gsum_ptr, 0, (size_t)G * D * sizeof(float));
    cudaMemsetAsync(cnt_ptr, 0, (size_t)G * sizeof(float));
    pool_kernel<<<(N + 7) / 8, 256>>>(h_ptr, gid, gsum_ptr, cnt_ptr, N);
    head_kernel<<<G, 256>>>(gsum_ptr, cnt_ptr, Wd, bd, out, G);
}

// round 13
// speedup vs baseline: 3.9747x; 1.1462x over previous
#include <cuda_runtime.h>
#include <cuda_bf16.h>
#include <math.h>
#include <stdint.h>

#define D 300
#define D2 600
#define LAYERS 5
#define MAXN 200000
#define MAXE 400000
#define MAXG 1024
#define BN_EPS 1e-5f

// ---- GEMM tiling ----
#define BM 64
#define BK 32
#define LDK 40            // halfwords per smem row (80B): conflict-free ldmatrix, 16B aligned
#define K1P 320           // GEMM1 K=300 padded
#define K2P 640           // GEMM2 K=600 padded (= t row stride)
#define N1P 640           // GEMM1 NC=600 padded (5 col tiles of 128)
#define N2P 320           // GEMM2 NC=300 padded (5 col tiles of 64)
#define ROWPAD 64
#define NSTAGES 3
#define STG_A   (BM * LDK * 2)            // 5120 B per A half

// ---------------- scratch (static device globals, zero-init .bss) ----------------
__device__ float g_h[(size_t)(MAXN + ROWPAD) * D];
__device__ float g_gsum[(size_t)MAXG * D];
__device__ float g_cnt[MAXG];
__device__ int g_rowptr[MAXN + 1];
__device__ int g_pos[MAXN];
__device__ uint32_t g_eidx[MAXE];
__device__ __nv_bfloat16 g_ah[(size_t)(MAXN + ROWPAD) * K1P];
__device__ __nv_bfloat16 g_al[(size_t)(MAXN + ROWPAD) * K1P];
__device__ __nv_bfloat16 g_th[(size_t)(MAXN + ROWPAD) * K2P];
__device__ __nv_bfloat16 g_tl[(size_t)(MAXN + ROWPAD) * K2P];
__device__ __nv_bfloat16 g_w1h[(size_t)LAYERS * N1P * K1P];
__device__ __nv_bfloat16 g_w1l[(size_t)LAYERS * N1P * K1P];
__device__ __nv_bfloat16 g_w2h[(size_t)LAYERS * N2P * K2P];
__device__ __nv_bfloat16 g_w2l[(size_t)LAYERS * N2P * K2P];

// ---------------- helpers ----------------
__device__ __forceinline__ uint32_t smem_u32(const void* p) {
    uint32_t a;
    asm("{ .reg .u64 t; cvta.to.shared.u64 t, %1; cvt.u32.u64 %0, t; }" : "=r"(a) : "l"(p));
    return a;
}
__device__ __forceinline__ void cp16(uint32_t dst, const void* src) {
    asm volatile("cp.async.cg.shared.global [%0], [%1], 16;" :: "r"(dst), "l"(src));
}
#define CP_COMMIT() asm volatile("cp.async.commit_group;" ::: "memory")
#define CP_WAIT1()  asm volatile("cp.async.wait_group 1;" ::: "memory")
__device__ __forceinline__ void ldsm_x4(uint32_t* r, uint32_t addr) {
    asm volatile("ldmatrix.sync.aligned.m8n8.x4.shared.b16 {%0,%1,%2,%3}, [%4];"
                 : "=r"(r[0]), "=r"(r[1]), "=r"(r[2]), "=r"(r[3]) : "r"(addr));
}
__device__ __forceinline__ void ldsm_x2(uint32_t* r, uint32_t addr) {
    asm volatile("ldmatrix.sync.aligned.m8n8.x2.shared.b16 {%0,%1}, [%2];"
                 : "=r"(r[0]), "=r"(r[1]) : "r"(addr));
}
__device__ __forceinline__ void mma_bf16(float* c, const uint32_t* a, const uint32_t* b) {
    asm volatile("mma.sync.aligned.m16n8k16.row.col.f32.bf16.bf16.f32 "
                 "{%0,%1,%2,%3}, {%4,%5,%6,%7}, {%8,%9}, {%0,%1,%2,%3};"
                 : "+f"(c[0]), "+f"(c[1]), "+f"(c[2]), "+f"(c[3])
                 : "r"(a[0]), "r"(a[1]), "r"(a[2]), "r"(a[3]), "r"(b[0]), "r"(b[1]));
}
__device__ __forceinline__ uint32_t pack2(float x0, float x1, float& r0, float& r1) {
    __nv_bfloat16 h0 = __float2bfloat16_rn(x0);
    __nv_bfloat16 h1 = __float2bfloat16_rn(x1);
    r0 = x0 - __bfloat162float(h0);
    r1 = x1 - __bfloat162float(h1);
    return ((uint32_t)__bfloat16_as_ushort(h1) << 16) | (uint32_t)__bfloat16_as_ushort(h0);
}
__device__ __forceinline__ uint32_t pack2lo(float r0, float r1) {
    __nv_bfloat16 l0 = __float2bfloat16_rn(r0);
    __nv_bfloat16 l1 = __float2bfloat16_rn(r1);
    return ((uint32_t)__bfloat16_as_ushort(l1) << 16) | (uint32_t)__bfloat16_as_ushort(l0);
}

// ---------------- launch 1: mega init (rowptr zero + node emb + weight split) ----------------
__global__ void mega_init_kernel(const int* __restrict__ an, const int* __restrict__ ct,
                                 const float* __restrict__ ne0, const float* __restrict__ ne1,
                                 const float* __restrict__ W1, const float* __restrict__ W2,
                                 float* __restrict__ h, int* __restrict__ rowptr,
                                 __nv_bfloat16* __restrict__ w1h, __nv_bfloat16* __restrict__ w1l,
                                 __nv_bfloat16* __restrict__ w2h, __nv_bfloat16* __restrict__ w2l,
                                 int N) {
    const int B0 = (MAXN + 1 + 255) / 256;
    const long NH = (long)MAXN * D;
    const int B1 = (int)((NH + 255) / 256);
    const int W1E = LAYERS * N1P * K1P;
    const int B2 = W1E / 256;
    int b = blockIdx.x;
    if (b < B0) {
        int idx = b * 256 + threadIdx.x;
        if (idx <= N) rowptr[idx] = 0;
    } else if (b < B0 + B1) {
        long idx = (long)(b - B0) * 256 + threadIdx.x;
        if (idx < (long)N * D) {
            int i = (int)(idx / D), d = (int)(idx - (long)i * D);
            h[idx] = ne0[(size_t)an[i] * D + d] + ne1[(size_t)ct[i] * D + d];
        }
    } else if (b < B0 + B1 + B2) {
        int idx = (b - B0 - B1) * 256 + threadIdx.x;
        int l = idx / (N1P * K1P);
        int lk = idx - l * (N1P * K1P);
        int n = lk / K1P, k = lk - n * K1P;
        float x = (n < D2 && k < D) ? W1[(size_t)l * D * D2 + (size_t)k * D2 + n] : 0.0f;
        __nv_bfloat16 hi = __float2bfloat16_rn(x);
        w1h[idx] = hi;
        w1l[idx] = __float2bfloat16_rn(x - __bfloat162float(hi));
    } else {
        int idx = (b - B0 - B1 - B2) * 256 + threadIdx.x;
        int l = idx / (N2P * K2P);
        int lk = idx - l * (N2P * K2P);
        int n = lk / K2P, k = lk - n * K2P;
        float x = (n < D && k < D2) ? W2[(size_t)l * D2 * D + (size_t)k * D + n] : 0.0f;
        __nv_bfloat16 hi = __float2bfloat16_rn(x);
        w2h[idx] = hi;
        w2l[idx] = __float2bfloat16_rn(x - __bfloat162float(hi));
    }
}

// ---------------- launch 2: degree histogram ----------------
__global__ void hist_kernel(const int* __restrict__ dst, int* __restrict__ rowptr, int E) {
    int e = blockIdx.x * 256 + threadIdx.x;
    if (e < E) atomicAdd(&rowptr[dst[e] + 1], 1);
}

// ---------------- launch 3: single-block inclusive scan + pos copy ----------------
__global__ void scan_kernel(int* __restrict__ rowptr, int* __restrict__ pos, int N) {
    __shared__ int ss[1024];
    int t = threadIdx.x;
    int n = N + 1;
    int len = (n + 1023) >> 10;
    int beg = t * len, end = beg + len;
    if (end > n) end = n;
    int s = 0;
    for (int i = beg; i < end; i++) s += rowptr[i];
    ss[t] = s;
    __syncthreads();
    for (int off = 1; off < 1024; off <<= 1) {
        int v = (t >= off) ? ss[t - off] : 0;
        __syncthreads();
        ss[t] += v;
        __syncthreads();
    }
    int run = (t > 0) ? ss[t - 1] : 0;
    for (int i = beg; i < end; i++) {
        run += rowptr[i];
        rowptr[i] = run;
        if (i < N) pos[i] = run;
    }
}

// ---------------- launch 4: scatter edges into CSR (packed src|bt|bd) ----------------
__global__ void scatter_kernel(const int* __restrict__ src, const int* __restrict__ dst,
                               const int* __restrict__ bt, const int* __restrict__ bd,
                               int* __restrict__ pos, uint32_t* __restrict__ eidx, int E) {
    int e = blockIdx.x * 256 + threadIdx.x;
    if (e >= E) return;
    int p = atomicAdd(&pos[dst[e]], 1);
    eidx[p] = (uint32_t)src[e] | ((uint32_t)bt[e] << 18) | ((uint32_t)bd[e] << 21);
}

// ---------------- per-layer: segmented message sum + split store ----------------
// ah/al[i] = split( sum_{e->i} h[src_e] + ee0[bt_e] + ee1[bd_e] )
__global__ void aggsplit_kernel(const float* __restrict__ h,
                                const float* __restrict__ ee0, const float* __restrict__ ee1,
                                const int* __restrict__ rowptr, const uint32_t* __restrict__ eidx,
                                __nv_bfloat16* __restrict__ ah, __nv_bfloat16* __restrict__ al,
                                int N) {
    int i = blockIdx.x * 8 + (threadIdx.x >> 5);
    if (i >= N) return;
    int lane = threadIdx.x & 31;
    float acc[10];
#pragma unroll
    for (int j = 0; j < 10; j++) acc[j] = 0.0f;
    int beg = rowptr[i], end = rowptr[i + 1];
    for (int e = beg; e < end; e++) {
        uint32_t p = eidx[e];
        const float* hs = h + (size_t)(p & 0x3FFFF) * D;
        const float* e0 = ee0 + (size_t)((p >> 18) & 7) * D;
        const float* e1 = ee1 + (size_t)(p >> 21) * D;
#pragma unroll
        for (int j = 0; j < 10; j++) {
            int d = lane + 32 * j;
            if (d < D) acc[j] += hs[d] + e0[d] + e1[d];
        }
    }
    size_t ro = (size_t)i * K1P;
#pragma unroll
    for (int j = 0; j < 10; j++) {
        int d = lane + 32 * j;
        if (d < D) {
            float x = acc[j];
            __nv_bfloat16 hi = __float2bfloat16_rn(x);
            ah[ro + d] = hi;
            al[ro + d] = __float2bfloat16_rn(x - __bfloat162float(hi));
        }
    }
}

// ---------------- pipelined split-bf16 mma.sync GEMM (templated tile width) ----------------
// BM=64 rows; warps 2x4; warp tile = 32 x (8*TN_T); BN_T = 32*TN_T
template<int BN_T, int TN_T>
__global__ void __launch_bounds__(256, 2)
gemm_pipe_kernel(const __nv_bfloat16* __restrict__ Ah, const __nv_bfloat16* __restrict__ Al,
                 const __nv_bfloat16* __restrict__ Bh, const __nv_bfloat16* __restrict__ Bl,
                 const float* __restrict__ bias,
                 __nv_bfloat16* __restrict__ Th, __nv_bfloat16* __restrict__ Tl,
                 float* __restrict__ Cf,
                 int M, int Kp, int NC, int mode,
                 const float* __restrict__ bn_g, const float* __restrict__ bn_b,
                 const float* __restrict__ bn_m, const float* __restrict__ bn_v) {
    constexpr int STG_B = BN_T * LDK * 2;
    constexpr int STAGE_BYTES = 2 * STG_A + 2 * STG_B;
    constexpr int NCHUNK = 512 + BN_T * 8;          // 16B cp.async chunks per stage
    constexpr int LCH = NCHUNK / 256;
    extern __shared__ __align__(16) char dsm[];
    const uint32_t sb = smem_u32(dsm);
    const int tid = threadIdx.x;
    const int wid = tid >> 5;
    const int lane = tid & 31;
    const int warp_m = wid >> 2;
    const int warp_n = wid & 3;
    const int row_base = blockIdx.y * BM;
    const int col_base = blockIdx.x * BN_T;
    const int nch = Kp / BK;

    const uint32_t a_lane = ((uint32_t)((lane & 15) * LDK + ((lane & 16) ? 8 : 0))) * 2;
    const uint32_t b_lane = ((uint32_t)((lane & 7) * LDK + ((lane & 8) ? 8 : 0))) * 2;

    float acc[2 * TN_T][4];
#pragma unroll
    for (int i = 0; i < 2 * TN_T; i++)
#pragma unroll
        for (int j = 0; j < 4; j++) acc[i][j] = 0.0f;

    auto load_stage = [&](int stg, int k0) {
        uint32_t base = sb + stg * STAGE_BYTES;
#pragma unroll
        for (int j = 0; j < LCH; j++) {
            int id = j * 256 + tid;
            uint32_t dst;
            const __nv_bfloat16* src;
            if (id < 512) {                       // A: 64 rows x 4 chunks x 2 halves
                int half = id >> 8;
                int q = id & 255;
                int r = q >> 2, c = q & 3;
                dst = base + half * STG_A + (uint32_t)(r * 80 + c * 16);
                src = (half ? Al : Ah) + (size_t)(row_base + r) * Kp + k0 + c * 8;
            } else {                              // B: BN_T rows x 4 chunks x 2 halves
                int id2 = id - 512;
                int half = id2 / (BN_T * 4);
                int q = id2 - half * (BN_T * 4);
                int r = q >> 2, c = q & 3;
                dst = base + 2 * STG_A + half * STG_B + (uint32_t)(r * 80 + c * 16);
                src = (half ? Bl : Bh) + (size_t)(col_base + r) * Kp + k0 + c * 8;
            }
            cp16(dst, src);
        }
    };

    load_stage(0, 0);
    CP_COMMIT();
    load_stage(1, BK);
    CP_COMMIT();

    for (int ch = 0; ch < nch; ch++) {
        CP_WAIT1();
        __syncthreads();
        if (ch + 2 < nch) load_stage((ch + 2) % NSTAGES, (ch + 2) * BK);
        CP_COMMIT();

        const uint32_t ah = sb + (ch % NSTAGES) * STAGE_BYTES;
        const uint32_t al = ah + STG_A;
        const uint32_t bh = ah + 2 * STG_A;
        const uint32_t bl = bh + STG_B;
#pragma unroll
        for (int ks = 0; ks < 2; ks++) {
            uint32_t af_h[2][4], af_l[2][4], bf_h[TN_T][2], bf_l[TN_T][2];
#pragma unroll
            for (int tm = 0; tm < 2; tm++) {
                uint32_t toff = (uint32_t)(((warp_m * 32 + tm * 16) * LDK + ks * 16) * 2) + a_lane;
                ldsm_x4(af_h[tm], ah + toff);
                ldsm_x4(af_l[tm], al + toff);
            }
#pragma unroll
            for (int tn = 0; tn < TN_T; tn++) {
                uint32_t toff = (uint32_t)(((warp_n * (8 * TN_T) + tn * 8) * LDK + ks * 16) * 2) + b_lane;
                ldsm_x2(bf_h[tn], bh + toff);
                ldsm_x2(bf_l[tn], bl + toff);
            }
#pragma unroll
            for (int tm = 0; tm < 2; tm++)
#pragma unroll
                for (int tn = 0; tn < TN_T; tn++) {
                    mma_bf16(acc[tm * TN_T + tn], af_h[tm], bf_h[tn]);
                    mma_bf16(acc[tm * TN_T + tn], af_h[tm], bf_l[tn]);
                    mma_bf16(acc[tm * TN_T + tn], af_l[tm], bf_h[tn]);
                }
        }
        __syncthreads();
    }

    // ---- epilogue ----
    const int r_base = row_base + warp_m * 32 + (lane >> 2);
    const int c_base2 = col_base + warp_n * (8 * TN_T) + (lane & 3) * 2;
#pragma unroll
    for (int tn = 0; tn < TN_T; tn++) {
        int c = c_base2 + tn * 8;
        if (c >= NC) continue;
        float bia0 = bias[c], bia1 = bias[c + 1];
        float sc0 = 0, sc1 = 0, mn0 = 0, mn1 = 0, bb0 = 0, bb1 = 0;
        if (!Th) {
            sc0 = bn_g[c] * rsqrtf(bn_v[c] + BN_EPS);
            sc1 = bn_g[c + 1] * rsqrtf(bn_v[c + 1] + BN_EPS);
            mn0 = bn_m[c]; mn1 = bn_m[c + 1];
            bb0 = bn_b[c]; bb1 = bn_b[c + 1];
        }
#pragma unroll
        for (int tm = 0; tm < 2; tm++) {
            const float* a4 = acc[tm * TN_T + tn];
#pragma unroll
            for (int half = 0; half < 2; half++) {
                int r = r_base + tm * 16 + half * 8;
                if (r >= M) continue;
                float x0 = a4[half * 2 + 0] + bia0;
                float x1 = a4[half * 2 + 1] + bia1;
                if (Th) {
                    x0 = fmaxf(x0, 0.0f); x1 = fmaxf(x1, 0.0f);
                    float r0, r1;
                    uint32_t hp = pack2(x0, x1, r0, r1);
                    uint32_t lp = pack2lo(r0, r1);
                    size_t off = (size_t)r * K2P + c;
                    *(uint32_t*)(Th + off) = hp;
                    *(uint32_t*)(Tl + off) = lp;
                } else {
                    x0 = (x0 - mn0) * sc0 + bb0;
                    x1 = (x1 - mn1) * sc1 + bb1;
                    if (mode == 2) { x0 = fmaxf(x0, 0.0f); x1 = fmaxf(x1, 0.0f); }
                    *(float2*)(Cf + (size_t)r * NC + c) = make_float2(x0, x1);
                }
            }
        }
    }
}

// ---------------- pooling + head ----------------
__global__ void pool_kernel(const float* __restrict__ h, const int* __restrict__ gid,
                            float* __restrict__ gsum, float* __restrict__ cnt, int N) {
    int i = blockIdx.x * 8 + (threadIdx.x >> 5);
    if (i >= N) return;
    int lane = threadIdx.x & 31;
    int g = gid[i];
    const float* hr = h + (size_t)i * D;
    float* out = gsum + (size_t)g * D;
    for (int d = lane; d < D; d += 32)
        atomicAdd(&out[d], hr[d]);
    if (lane == 0)
        atomicAdd(&cnt[g], 1.0f);
}

__global__ void head_kernel(const float* __restrict__ gsum, const float* __restrict__ cnt,
                            const float* __restrict__ Wd, const float* __restrict__ bd,
                            float* __restrict__ out, int G) {
    __shared__ float row[D];
    int g = blockIdx.x;
    if (g >= G) return;
    float inv = 1.0f / fmaxf(cnt[g], 1.0f);
    for (int k = threadIdx.x; k < D; k += blockDim.x)
        row[k] = gsum[(size_t)g * D + k] * inv;
    __syncthreads();
    int c = threadIdx.x;
    float acc = bd[c];
#pragma unroll 4
    for (int k = 0; k < D; k++)
        acc = fmaf(row[k], Wd[(size_t)k * 256 + c], acc);
    out[(size_t)g * 256 + c] = acc;
}

// ---------------- launch ----------------
extern "C" void kernel_launch(void* const* d_in, const int* in_sizes, int n_in,
                              void* d_out, int out_size) {
    const int*   atomic_number = (const int*)d_in[0];
    const int*   chirality     = (const int*)d_in[1];
    const int*   bond_type     = (const int*)d_in[2];
    const int*   bond_dir      = (const int*)d_in[3];
    const int*   src           = (const int*)d_in[4];
    const int*   dst           = (const int*)d_in[5];
    const int*   gid           = (const int*)d_in[6];
    const float* ne0           = (const float*)d_in[8];
    const float* ne1           = (const float*)d_in[9];
    const float* ee0           = (const float*)d_in[10];
    const float* ee1           = (const float*)d_in[11];
    const float* W1            = (const float*)d_in[12];
    const float* b1            = (const float*)d_in[13];
    const float* W2            = (const float*)d_in[14];
    const float* b2            = (const float*)d_in[15];
    const float* gamma         = (const float*)d_in[16];
    const float* beta          = (const float*)d_in[17];
    const float* mean          = (const float*)d_in[18];
    const float* var           = (const float*)d_in[19];
    const float* Wd            = (const float*)d_in[20];
    const float* bd            = (const float*)d_in[21];
    float* out = (float*)d_out;

    int N = in_sizes[0];
    int E = in_sizes[2];
    int G = out_size / 256;
    if (N > MAXN) N = MAXN;
    if (E > MAXE) E = MAXE;
    if (G > MAXG) G = MAXG;

    constexpr int SMEM1 = NSTAGES * (2 * STG_A + 2 * 128 * LDK * 2);  // 92160
    constexpr int SMEM2 = NSTAGES * (2 * STG_A + 2 * 64 * LDK * 2);   // 61440
    static int attr_set = 0;
    if (!attr_set) {
        cudaFuncSetAttribute(gemm_pipe_kernel<128, 4>, cudaFuncAttributeMaxDynamicSharedMemorySize, SMEM1);
        cudaFuncSetAttribute(gemm_pipe_kernel<64, 2>, cudaFuncAttributeMaxDynamicSharedMemorySize, SMEM2);
        attr_set = 1;
    }

    float *h_ptr, *gsum_ptr, *cnt_ptr;
    int *rowptr, *pos;
    uint32_t* eidx;
    __nv_bfloat16 *ah, *al, *th, *tl, *w1h, *w1l, *w2h, *w2l;
    cudaGetSymbolAddress((void**)&h_ptr, g_h);
    cudaGetSymbolAddress((void**)&gsum_ptr, g_gsum);
    cudaGetSymbolAddress((void**)&cnt_ptr, g_cnt);
    cudaGetSymbolAddress((void**)&rowptr, g_rowptr);
    cudaGetSymbolAddress((void**)&pos, g_pos);
    cudaGetSymbolAddress((void**)&eidx, g_eidx);
    cudaGetSymbolAddress((void**)&ah, g_ah);
    cudaGetSymbolAddress((void**)&al, g_al);
    cudaGetSymbolAddress((void**)&th, g_th);
    cudaGetSymbolAddress((void**)&tl, g_tl);
    cudaGetSymbolAddress((void**)&w1h, g_w1h);
    cudaGetSymbolAddress((void**)&w1l, g_w1l);
    cudaGetSymbolAddress((void**)&w2h, g_w2h);
    cudaGetSymbolAddress((void**)&w2l, g_w2l);

    // launch 1: fused init (rowptr zero + node emb + weight transpose/split)
    {
        const int B0 = (MAXN + 1 + 255) / 256;
        const int B1 = (int)(((long)MAXN * D + 255) / 256);
        const int B2 = LAYERS * N1P * K1P / 256;
        const int B3 = LAYERS * N2P * K2P / 256;
        mega_init_kernel<<<B0 + B1 + B2 + B3, 256>>>(
            atomic_number, chirality, ne0, ne1, W1, W2,
            h_ptr, rowptr, w1h, w1l, w2h, w2l, N);
    }
    // launches 2-4: CSR build
    hist_kernel<<<(E + 255) / 256, 256>>>(dst, rowptr, E);
    scan_kernel<<<1, 1024>>>(rowptr, pos, N);
    scatter_kernel<<<(E + 255) / 256, 256>>>(src, dst, bond_type, bond_dir, pos, eidx, E);

    const int nrb = (N + BM - 1) / BM;
    for (int l = 0; l < LAYERS; l++) {
        // fused message-sum + bf16 split (launch 5 for l=0)
        aggsplit_kernel<<<(N + 7) / 8, 256>>>(h_ptr,
                                              ee0 + (size_t)l * 6 * D,
                                              ee1 + (size_t)l * 3 * D,
                                              rowptr, eidx, ah, al, N);
        // GEMM1: t = relu(agg @ W1 + b1), split-stored (launch 6 for l=0 -> ncu target)
        {
            dim3 grid(N1P / 128, nrb);
            gemm_pipe_kernel<128, 4><<<grid, 256, SMEM1>>>(
                ah, al, w1h + (size_t)l * N1P * K1P, w1l + (size_t)l * N1P * K1P,
                b1 + (size_t)l * D2, th, tl, nullptr,
                N, K1P, D2, 0, nullptr, nullptr, nullptr, nullptr);
        }
        // GEMM2: h = [relu](BN(t @ W2 + b2)), BN=64 tiles (N2P=320)
        {
            dim3 grid(N2P / 64, nrb);
            int mode = (l < LAYERS - 1) ? 2 : 1;
            gemm_pipe_kernel<64, 2><<<grid, 256, SMEM2>>>(
                th, tl, w2h + (size_t)l * N2P * K2P, w2l + (size_t)l * N2P * K2P,
                b2 + (size_t)l * D, nullptr, nullptr, h_ptr,
                N, K2P, D, mode,
                gamma + (size_t)l * D, beta + (size_t)l * D,
                mean + (size_t)l * D, var + (size_t)l * D);
        }
    }

    cudaMemsetAsync(gsum_ptr, 0, (size_t)G * D * sizeof(float));
    cudaMemsetAsync(cnt_ptr, 0, (size_t)G * sizeof(float));
    pool_kernel<<<(N + 7) / 8, 256>>>(h_ptr, gid, gsum_ptr, cnt_ptr, N);
    head_kernel<<<G, 256>>>(gsum_ptr, cnt_ptr, Wd, bd, out, G);
}

// round 15
// speedup vs baseline: 4.0368x; 1.0156x over previous
#include <cuda_runtime.h>
#include <cuda_bf16.h>
#include <math.h>
#include <stdint.h>

#define D 300
#define D2 600
#define LAYERS 5
#define MAXN 200000
#define MAXE 400000
#define MAXG 1024
#define BN_EPS 1e-5f

// ---- GEMM tiling ----
#define BM 64
#define BK 32
#define LDK 40            // halfwords per smem row (80B): conflict-free ldmatrix, 16B aligned
#define K1P 320           // GEMM1 K=300 padded (storage stride AND compute K)
#define K2P 640           // t row storage stride
#define K2C 608           // GEMM2 compute K (19 x 32; [600,608) zero pad)
#define N1P 640           // GEMM1 NC=600 padded (5 col tiles of 128)
#define N2P 320           // GEMM2 NC=300 padded (5 col tiles of 64)
#define ROWPAD 64
#define NSTAGES 3
#define STG_A   (BM * LDK * 2)            // 5120 B per A half

// ---------------- scratch (static device globals, zero-init .bss) ----------------
__device__ float g_h[(size_t)(MAXN + ROWPAD) * D];
__device__ float g_gsum[(size_t)MAXG * D];
__device__ float g_cnt[MAXG];
__device__ int g_deg[MAXN + 1];      // zeroed by scan after reading (invariant)
__device__ int g_rowptr[MAXN + 1];
__device__ int g_pos[MAXN];
__device__ uint32_t g_eidx[MAXE];
__device__ __nv_bfloat16 g_ah[(size_t)(MAXN + ROWPAD) * K1P];
__device__ __nv_bfloat16 g_al[(size_t)(MAXN + ROWPAD) * K1P];
__device__ __nv_bfloat16 g_th[(size_t)(MAXN + ROWPAD) * K2P];
__device__ __nv_bfloat16 g_tl[(size_t)(MAXN + ROWPAD) * K2P];
__device__ __nv_bfloat16 g_w1h[(size_t)LAYERS * N1P * K1P];
__device__ __nv_bfloat16 g_w1l[(size_t)LAYERS * N1P * K1P];
__device__ __nv_bfloat16 g_w2h[(size_t)LAYERS * N2P * K2P];
__device__ __nv_bfloat16 g_w2l[(size_t)LAYERS * N2P * K2P];

// ---------------- helpers ----------------
__device__ __forceinline__ uint32_t smem_u32(const void* p) {
    uint32_t a;
    asm("{ .reg .u64 t; cvta.to.shared.u64 t, %1; cvt.u32.u64 %0, t; }" : "=r"(a) : "l"(p));
    return a;
}
__device__ __forceinline__ void cp16(uint32_t dst, const void* src) {
    asm volatile("cp.async.cg.shared.global [%0], [%1], 16;" :: "r"(dst), "l"(src));
}
#define CP_COMMIT() asm volatile("cp.async.commit_group;" ::: "memory")
#define CP_WAIT1()  asm volatile("cp.async.wait_group 1;" ::: "memory")
__device__ __forceinline__ void ldsm_x4(uint32_t* r, uint32_t addr) {
    asm volatile("ldmatrix.sync.aligned.m8n8.x4.shared.b16 {%0,%1,%2,%3}, [%4];"
                 : "=r"(r[0]), "=r"(r[1]), "=r"(r[2]), "=r"(r[3]) : "r"(addr));
}
__device__ __forceinline__ void ldsm_x2(uint32_t* r, uint32_t addr) {
    asm volatile("ldmatrix.sync.aligned.m8n8.x2.shared.b16 {%0,%1}, [%2];"
                 : "=r"(r[0]), "=r"(r[1]) : "r"(addr));
}
__device__ __forceinline__ void mma_bf16(float* c, const uint32_t* a, const uint32_t* b) {
    asm volatile("mma.sync.aligned.m16n8k16.row.col.f32.bf16.bf16.f32 "
                 "{%0,%1,%2,%3}, {%4,%5,%6,%7}, {%8,%9}, {%0,%1,%2,%3};"
                 : "+f"(c[0]), "+f"(c[1]), "+f"(c[2]), "+f"(c[3])
                 : "r"(a[0]), "r"(a[1]), "r"(a[2]), "r"(a[3]), "r"(b[0]), "r"(b[1]));
}
__device__ __forceinline__ uint32_t pack2(float x0, float x1, float& r0, float& r1) {
    __nv_bfloat16 h0 = __float2bfloat16_rn(x0);
    __nv_bfloat16 h1 = __float2bfloat16_rn(x1);
    r0 = x0 - __bfloat162float(h0);
    r1 = x1 - __bfloat162float(h1);
    return ((uint32_t)__bfloat16_as_ushort(h1) << 16) | (uint32_t)__bfloat16_as_ushort(h0);
}
__device__ __forceinline__ uint32_t pack2lo(float r0, float r1) {
    __nv_bfloat16 l0 = __float2bfloat16_rn(r0);
    __nv_bfloat16 l1 = __float2bfloat16_rn(r1);
    return ((uint32_t)__bfloat16_as_ushort(l1) << 16) | (uint32_t)__bfloat16_as_ushort(l0);
}

// -------- launch 1: mega init (hist atomics + node emb + weight split) --------
// deg is pre-zeroed: .bss on first call, re-zeroed by scan_kernel on every call.
__global__ void mega_init_kernel(const int* __restrict__ an, const int* __restrict__ ct,
                                 const int* __restrict__ dst,
                                 const float* __restrict__ ne0, const float* __restrict__ ne1,
                                 const float* __restrict__ W1, const float* __restrict__ W2,
                                 float* __restrict__ h, int* __restrict__ deg,
                                 __nv_bfloat16* __restrict__ w1h, __nv_bfloat16* __restrict__ w1l,
                                 __nv_bfloat16* __restrict__ w2h, __nv_bfloat16* __restrict__ w2l,
                                 int N, int E) {
    const int BH = (MAXE + 255) / 256;
    const long NH = (long)MAXN * D;
    const int B1 = (int)((NH + 255) / 256);
    const int B2 = LAYERS * N1P * K1P / 256;
    int b = blockIdx.x;
    if (b < BH) {
        int e = b * 256 + threadIdx.x;
        if (e < E) atomicAdd(&deg[dst[e] + 1], 1);
    } else if (b < BH + B1) {
        long idx = (long)(b - BH) * 256 + threadIdx.x;
        if (idx < (long)N * D) {
            int i = (int)(idx / D), d = (int)(idx - (long)i * D);
            h[idx] = ne0[(size_t)an[i] * D + d] + ne1[(size_t)ct[i] * D + d];
        }
    } else if (b < BH + B1 + B2) {
        int idx = (b - BH - B1) * 256 + threadIdx.x;
        int l = idx / (N1P * K1P);
        int lk = idx - l * (N1P * K1P);
        int n = lk / K1P, k = lk - n * K1P;
        float x = (n < D2 && k < D) ? W1[(size_t)l * D * D2 + (size_t)k * D2 + n] : 0.0f;
        __nv_bfloat16 hi = __float2bfloat16_rn(x);
        w1h[idx] = hi;
        w1l[idx] = __float2bfloat16_rn(x - __bfloat162float(hi));
    } else {
        int idx = (b - BH - B1 - B2) * 256 + threadIdx.x;
        int l = idx / (N2P * K2P);
        int lk = idx - l * (N2P * K2P);
        int n = lk / K2P, k = lk - n * K2P;
        float x = (n < D && k < D2) ? W2[(size_t)l * D2 * D + (size_t)k * D + n] : 0.0f;
        __nv_bfloat16 hi = __float2bfloat16_rn(x);
        w2h[idx] = hi;
        w2l[idx] = __float2bfloat16_rn(x - __bfloat162float(hi));
    }
}

// -------- launch 2: single-block inclusive scan; reads deg, zeroes it for next call --------
__global__ void scan_kernel(int* __restrict__ deg, int* __restrict__ rowptr,
                            int* __restrict__ pos, int N) {
    __shared__ int ss[1024];
    int t = threadIdx.x;
    int n = N + 1;
    int len = (n + 1023) >> 10;
    int beg = t * len, end = beg + len;
    if (end > n) end = n;
    int s = 0;
    for (int i = beg; i < end; i++) s += deg[i];
    ss[t] = s;
    __syncthreads();
    for (int off = 1; off < 1024; off <<= 1) {
        int v = (t >= off) ? ss[t - off] : 0;
        __syncthreads();
        ss[t] += v;
        __syncthreads();
    }
    int run = (t > 0) ? ss[t - 1] : 0;
    for (int i = beg; i < end; i++) {
        run += deg[i];
        deg[i] = 0;                     // restore invariant for next replay
        rowptr[i] = run;
        if (i < N) pos[i] = run;
    }
}

// -------- launch 3: scatter edges into CSR (packed src|bt|bd) --------
__global__ void scatter_kernel(const int* __restrict__ src, const int* __restrict__ dst,
                               const int* __restrict__ bt, const int* __restrict__ bd,
                               int* __restrict__ pos, uint32_t* __restrict__ eidx, int E) {
    int e = blockIdx.x * 256 + threadIdx.x;
    if (e >= E) return;
    int p = atomicAdd(&pos[dst[e]], 1);
    eidx[p] = (uint32_t)src[e] | ((uint32_t)bt[e] << 18) | ((uint32_t)bd[e] << 21);
}

// -------- launch 4 (= ncu capture slot): segmented message sum + split store --------
// ah/al[i] = split( sum_{e->i} h[src_e] + ee0[bt_e] + ee1[bd_e] ), float2 path
__global__ void aggsplit_kernel(const float* __restrict__ h,
                                const float* __restrict__ ee0, const float* __restrict__ ee1,
                                const int* __restrict__ rowptr, const uint32_t* __restrict__ eidx,
                                __nv_bfloat16* __restrict__ ah, __nv_bfloat16* __restrict__ al,
                                int N) {
    int i = blockIdx.x * 8 + (threadIdx.x >> 5);
    if (i >= N) return;
    int lane = threadIdx.x & 31;
    float2 acc[5];
#pragma unroll
    for (int j = 0; j < 5; j++) acc[j] = make_float2(0.0f, 0.0f);
    int beg = rowptr[i], end = rowptr[i + 1];
    for (int e = beg; e < end; e++) {
        uint32_t p = eidx[e];
        const float2* hs = (const float2*)(h + (size_t)(p & 0x3FFFF) * D);
        const float2* e0 = (const float2*)(ee0 + (size_t)((p >> 18) & 7) * D);
        const float2* e1 = (const float2*)(ee1 + (size_t)(p >> 21) * D);
#pragma unroll
        for (int j = 0; j < 5; j++) {
            int pr = lane + 32 * j;
            if (pr < 150) {
                float2 a = hs[pr], b = e0[pr], c = e1[pr];
                acc[j].x += a.x + b.x + c.x;
                acc[j].y += a.y + b.y + c.y;
            }
        }
    }
    size_t ro = (size_t)i * K1P;
#pragma unroll
    for (int j = 0; j < 5; j++) {
        int pr = lane + 32 * j;
        if (pr < 150) {
            float r0, r1;
            uint32_t hp = pack2(acc[j].x, acc[j].y, r0, r1);
            uint32_t lp = pack2lo(r0, r1);
            *(uint32_t*)(ah + ro + pr * 2) = hp;
            *(uint32_t*)(al + ro + pr * 2) = lp;
        }
    }
}

// ---------------- pipelined split-bf16 mma.sync GEMM (templated tile width) ----------------
// BM=64 rows; warps 2x4; warp tile = 32 x (8*TN_T); BN_T = 32*TN_T
// Kp = compute K (multiple of BK); ldA/ldB = row strides in halfwords (>= Kp)
template<int BN_T, int TN_T>
__global__ void __launch_bounds__(256, 2)
gemm_pipe_kernel(const __nv_bfloat16* __restrict__ Ah, const __nv_bfloat16* __restrict__ Al,
                 const __nv_bfloat16* __restrict__ Bh, const __nv_bfloat16* __restrict__ Bl,
                 const float* __restrict__ bias,
                 __nv_bfloat16* __restrict__ Th, __nv_bfloat16* __restrict__ Tl,
                 float* __restrict__ Cf,
                 int M, int Kp, int ldA, int ldB, int NC, int mode,
                 const float* __restrict__ bn_g, const float* __restrict__ bn_b,
                 const float* __restrict__ bn_m, const float* __restrict__ bn_v) {
    constexpr int STG_B = BN_T * LDK * 2;
    constexpr int STAGE_BYTES = 2 * STG_A + 2 * STG_B;
    constexpr int NCHUNK = 512 + BN_T * 8;          // 16B cp.async chunks per stage
    constexpr int LCH = NCHUNK / 256;
    extern __shared__ __align__(16) char dsm[];
    const uint32_t sb = smem_u32(dsm);
    const int tid = threadIdx.x;
    const int wid = tid >> 5;
    const int lane = tid & 31;
    const int warp_m = wid >> 2;
    const int warp_n = wid & 3;
    const int row_base = blockIdx.y * BM;
    const int col_base = blockIdx.x * BN_T;
    const int nch = Kp / BK;

    const uint32_t a_lane = ((uint32_t)((lane & 15) * LDK + ((lane & 16) ? 8 : 0))) * 2;
    const uint32_t b_lane = ((uint32_t)((lane & 7) * LDK + ((lane & 8) ? 8 : 0))) * 2;

    float acc[2 * TN_T][4];
#pragma unroll
    for (int i = 0; i < 2 * TN_T; i++)
#pragma unroll
        for (int j = 0; j < 4; j++) acc[i][j] = 0.0f;

    auto load_stage = [&](int stg, int k0) {
        uint32_t base = sb + stg * STAGE_BYTES;
#pragma unroll
        for (int j = 0; j < LCH; j++) {
            int id = j * 256 + tid;
            uint32_t dst;
            const __nv_bfloat16* src;
            if (id < 512) {                       // A: 64 rows x 4 chunks x 2 halves
                int half = id >> 8;
                int q = id & 255;
                int r = q >> 2, c = q & 3;
                dst = base + half * STG_A + (uint32_t)(r * 80 + c * 16);
                src = (half ? Al : Ah) + (size_t)(row_base + r) * ldA + k0 + c * 8;
            } else {                              // B: BN_T rows x 4 chunks x 2 halves
                int id2 = id - 512;
                int half = id2 / (BN_T * 4);
                int q = id2 - half * (BN_T * 4);
                int r = q >> 2, c = q & 3;
                dst = base + 2 * STG_A + half * STG_B + (uint32_t)(r * 80 + c * 16);
                src = (half ? Bl : Bh) + (size_t)(col_base + r) * ldB + k0 + c * 8;
            }
            cp16(dst, src);
        }
    };

    load_stage(0, 0);
    CP_COMMIT();
    load_stage(1, BK);
    CP_COMMIT();

    for (int ch = 0; ch < nch; ch++) {
        CP_WAIT1();
        __syncthreads();
        if (ch + 2 < nch) load_stage((ch + 2) % NSTAGES, (ch + 2) * BK);
        CP_COMMIT();

        const uint32_t ah = sb + (ch % NSTAGES) * STAGE_BYTES;
        const uint32_t al = ah + STG_A;
        const uint32_t bh = ah + 2 * STG_A;
        const uint32_t bl = bh + STG_B;
#pragma unroll
        for (int ks = 0; ks < 2; ks++) {
            uint32_t af_h[2][4], af_l[2][4], bf_h[TN_T][2], bf_l[TN_T][2];
#pragma unroll
            for (int tm = 0; tm < 2; tm++) {
                uint32_t toff = (uint32_t)(((warp_m * 32 + tm * 16) * LDK + ks * 16) * 2) + a_lane;
                ldsm_x4(af_h[tm], ah + toff);
                ldsm_x4(af_l[tm], al + toff);
            }
#pragma unroll
            for (int tn = 0; tn < TN_T; tn++) {
                uint32_t toff = (uint32_t)(((warp_n * (8 * TN_T) + tn * 8) * LDK + ks * 16) * 2) + b_lane;
                ldsm_x2(bf_h[tn], bh + toff);
                ldsm_x2(bf_l[tn], bl + toff);
            }
#pragma unroll
            for (int tm = 0; tm < 2; tm++)
#pragma unroll
                for (int tn = 0; tn < TN_T; tn++) {
                    mma_bf16(acc[tm * TN_T + tn], af_h[tm], bf_h[tn]);
                    mma_bf16(acc[tm * TN_T + tn], af_h[tm], bf_l[tn]);
                    mma_bf16(acc[tm * TN_T + tn], af_l[tm], bf_h[tn]);
                }
        }
        __syncthreads();
    }

    // ---- epilogue ----
    const int r_base = row_base + warp_m * 32 + (lane >> 2);
    const int c_base2 = col_base + warp_n * (8 * TN_T) + (lane & 3) * 2;
#pragma unroll
    for (int tn = 0; tn < TN_T; tn++) {
        int c = c_base2 + tn * 8;
        if (c >= NC) continue;
        float bia0 = bias[c], bia1 = bias[c + 1];
        float sc0 = 0, sc1 = 0, mn0 = 0, mn1 = 0, bb0 = 0, bb1 = 0;
        if (!Th) {
            sc0 = bn_g[c] * rsqrtf(bn_v[c] + BN_EPS);
            sc1 = bn_g[c + 1] * rsqrtf(bn_v[c + 1] + BN_EPS);
            mn0 = bn_m[c]; mn1 = bn_m[c + 1];
            bb0 = bn_b[c]; bb1 = bn_b[c + 1];
        }
#pragma unroll
        for (int tm = 0; tm < 2; tm++) {
            const float* a4 = acc[tm * TN_T + tn];
#pragma unroll
            for (int half = 0; half < 2; half++) {
                int r = r_base + tm * 16 + half * 8;
                if (r >= M) continue;
                float x0 = a4[half * 2 + 0] + bia0;
                float x1 = a4[half * 2 + 1] + bia1;
                if (Th) {
                    x0 = fmaxf(x0, 0.0f); x1 = fmaxf(x1, 0.0f);
                    float r0, r1;
                    uint32_t hp = pack2(x0, x1, r0, r1);
                    uint32_t lp = pack2lo(r0, r1);
                    size_t off = (size_t)r * K2P + c;
                    *(uint32_t*)(Th + off) = hp;
                    *(uint32_t*)(Tl + off) = lp;
                } else {
                    x0 = (x0 - mn0) * sc0 + bb0;
                    x1 = (x1 - mn1) * sc1 + bb1;
                    if (mode == 2) { x0 = fmaxf(x0, 0.0f); x1 = fmaxf(x1, 0.0f); }
                    *(float2*)(Cf + (size_t)r * NC + c) = make_float2(x0, x1);
                }
            }
        }
    }
}

// ---------------- pooling + head ----------------
__global__ void pool_kernel(const float* __restrict__ h, const int* __restrict__ gid,
                            float* __restrict__ gsum, float* __restrict__ cnt, int N) {
    int i = blockIdx.x * 8 + (threadIdx.x >> 5);
    if (i >= N) return;
    int lane = threadIdx.x & 31;
    int g = gid[i];
    const float* hr = h + (size_t)i * D;
    float* out = gsum + (size_t)g * D;
    for (int d = lane; d < D; d += 32)
        atomicAdd(&out[d], hr[d]);
    if (lane == 0)
        atomicAdd(&cnt[g], 1.0f);
}

__global__ void head_kernel(const float* __restrict__ gsum, const float* __restrict__ cnt,
                            const float* __restrict__ Wd, const float* __restrict__ bd,
                            float* __restrict__ out, int G) {
    __shared__ float row[D];
    int g = blockIdx.x;
    if (g >= G) return;
    float inv = 1.0f / fmaxf(cnt[g], 1.0f);
    for (int k = threadIdx.x; k < D; k += blockDim.x)
        row[k] = gsum[(size_t)g * D + k] * inv;
    __syncthreads();
    int c = threadIdx.x;
    float acc = bd[c];
#pragma unroll 4
    for (int k = 0; k < D; k++)
        acc = fmaf(row[k], Wd[(size_t)k * 256 + c], acc);
    out[(size_t)g * 256 + c] = acc;
}

// ---------------- launch ----------------
extern "C" void kernel_launch(void* const* d_in, const int* in_sizes, int n_in,
                              void* d_out, int out_size) {
    const int*   atomic_number = (const int*)d_in[0];
    const int*   chirality     = (const int*)d_in[1];
    const int*   bond_type     = (const int*)d_in[2];
    const int*   bond_dir      = (const int*)d_in[3];
    const int*   src           = (const int*)d_in[4];
    const int*   dst           = (const int*)d_in[5];
    const int*   gid           = (const int*)d_in[6];
    const float* ne0           = (const float*)d_in[8];
    const float* ne1           = (const float*)d_in[9];
    const float* ee0           = (const float*)d_in[10];
    const float* ee1           = (const float*)d_in[11];
    const float* W1            = (const float*)d_in[12];
    const float* b1            = (const float*)d_in[13];
    const float* W2            = (const float*)d_in[14];
    const float* b2            = (const float*)d_in[15];
    const float* gamma         = (const float*)d_in[16];
    const float* beta          = (const float*)d_in[17];
    const float* mean          = (const float*)d_in[18];
    const float* var           = (const float*)d_in[19];
    const float* Wd            = (const float*)d_in[20];
    const float* bd            = (const float*)d_in[21];
    float* out = (float*)d_out;

    int N = in_sizes[0];
    int E = in_sizes[2];
    int G = out_size / 256;
    if (N > MAXN) N = MAXN;
    if (E > MAXE) E = MAXE;
    if (G > MAXG) G = MAXG;

    constexpr int SMEM1 = NSTAGES * (2 * STG_A + 2 * 128 * LDK * 2);  // 92160
    constexpr int SMEM2 = NSTAGES * (2 * STG_A + 2 * 64 * LDK * 2);   // 61440
    static int attr_set = 0;
    if (!attr_set) {
        cudaFuncSetAttribute(gemm_pipe_kernel<128, 4>, cudaFuncAttributeMaxDynamicSharedMemorySize, SMEM1);
        cudaFuncSetAttribute(gemm_pipe_kernel<64, 2>, cudaFuncAttributeMaxDynamicSharedMemorySize, SMEM2);
        attr_set = 1;
    }

    float *h_ptr, *gsum_ptr, *cnt_ptr;
    int *deg, *rowptr, *pos;
    uint32_t* eidx;
    __nv_bfloat16 *ah, *al, *th, *tl, *w1h, *w1l, *w2h, *w2l;
    cudaGetSymbolAddress((void**)&h_ptr, g_h);
    cudaGetSymbolAddress((void**)&gsum_ptr, g_gsum);
    cudaGetSymbolAddress((void**)&cnt_ptr, g_cnt);
    cudaGetSymbolAddress((void**)&deg, g_deg);
    cudaGetSymbolAddress((void**)&rowptr, g_rowptr);
    cudaGetSymbolAddress((void**)&pos, g_pos);
    cudaGetSymbolAddress((void**)&eidx, g_eidx);
    cudaGetSymbolAddress((void**)&ah, g_ah);
    cudaGetSymbolAddress((void**)&al, g_al);
    cudaGetSymbolAddress((void**)&th, g_th);
    cudaGetSymbolAddress((void**)&tl, g_tl);
    cudaGetSymbolAddress((void**)&w1h, g_w1h);
    cudaGetSymbolAddress((void**)&w1l, g_w1l);
    cudaGetSymbolAddress((void**)&w2h, g_w2h);
    cudaGetSymbolAddress((void**)&w2l, g_w2l);

    // launch 1: fused init (hist + node emb + weight transpose/split)
    {
        const int BH = (MAXE + 255) / 256;
        const int B1 = (int)(((long)MAXN * D + 255) / 256);
        const int B2 = LAYERS * N1P * K1P / 256;
        const int B3 = LAYERS * N2P * K2P / 256;
        mega_init_kernel<<<BH + B1 + B2 + B3, 256>>>(
            atomic_number, chirality, dst, ne0, ne1, W1, W2,
            h_ptr, deg, w1h, w1l, w2h, w2l, N, E);
    }
    // launch 2: scan (reads deg, zeroes it, writes rowptr/pos)
    scan_kernel<<<1, 1024>>>(deg, rowptr, pos, N);
    // launch 3: scatter
    scatter_kernel<<<(E + 255) / 256, 256>>>(src, dst, bond_type, bond_dir, pos, eidx, E);

    const int nrb = (N + BM - 1) / BM;
    for (int l = 0; l < LAYERS; l++) {
        // launch 4 on l=0: fused message-sum + bf16 split (ncu capture slot)
        aggsplit_kernel<<<(N + 7) / 8, 256>>>(h_ptr,
                                              ee0 + (size_t)l * 6 * D,
                                              ee1 + (size_t)l * 3 * D,
                                              rowptr, eidx, ah, al, N);
        // GEMM1: t = relu(agg @ W1 + b1), split-stored
        {
            dim3 grid(N1P / 128, nrb);
            gemm_pipe_kernel<128, 4><<<grid, 256, SMEM1>>>(
                ah, al, w1h + (size_t)l * N1P * K1P, w1l + (size_t)l * N1P * K1P,
                b1 + (size_t)l * D2, th, tl, nullptr,
                N, K1P, K1P, K1P, D2, 0, nullptr, nullptr, nullptr, nullptr);
        }
        // GEMM2: h = [relu](BN(t @ W2 + b2)); compute K = 608, strides 640
        {
            dim3 grid(N2P / 64, nrb);
            int mode = (l < LAYERS - 1) ? 2 : 1;
            gemm_pipe_kernel<64, 2><<<grid, 256, SMEM2>>>(
                th, tl, w2h + (size_t)l * N2P * K2P, w2l + (size_t)l * N2P * K2P,
                b2 + (size_t)l * D, nullptr, nullptr, h_ptr,
                N, K2C, K2P, K2P, D, mode,
                gamma + (size_t)l * D, beta + (size_t)l * D,
                mean + (size_t)l * D, var + (size_t)l * D);
        }
    }

    cudaMemsetAsync(gsum_ptr, 0, (size_t)G * D * sizeof(float));
    cudaMemsetAsync(cnt_ptr, 0, (size_t)G * sizeof(float));
    pool_kernel<<<(N + 7) / 8, 256>>>(h_ptr, gid, gsum_ptr, cnt_ptr, N);
    head_kernel<<<G, 256>>>(gsum_ptr, cnt_ptr, Wd, bd, out, G);
}